// round 10
// baseline (speedup 1.0000x reference)
#include <cuda_runtime.h>
#include <math.h>
#include <stdint.h>

#define DMODEL 1024
#define NHEADS 8
#define DK 128
#define BB 2
#define SS 2048
#define NZ (BB * NHEADS)          // 16
#define NTILE (SS / 128)          // 16

// Scratch (allocation-free rule: __device__ globals)
__device__ float g_q[(size_t)BB * SS * DMODEL];
__device__ float g_k[(size_t)BB * SS * DMODEL];
__device__ float g_v[(size_t)BB * SS * DMODEL];
__device__ float g_vt[(size_t)BB * NHEADS * DK * SS];
__device__ float g_ctx[(size_t)BB * SS * DMODEL];
__device__ float g_raw[(size_t)NZ * SS * SS];
__device__ float g_statsM[(size_t)NZ * SS * NTILE];
__device__ float g_statsS[(size_t)NZ * SS * NTILE];
__device__ float g_rowM[(size_t)NZ * SS];
__device__ float g_rowInv[(size_t)NZ * SS];
__device__ float g_w[4][(size_t)DMODEL * DMODEL];      // tf32-rounded weights
__device__ float g_in[3][(size_t)BB * SS * DMODEL];    // tf32-rounded Q,K,V inputs

__device__ __forceinline__ uint32_t smem_u32(const void* p) {
    uint32_t a;
    asm("{ .reg .u64 t; cvta.to.shared.u64 t, %1; cvt.u32.u64 %0, t; }" : "=r"(a) : "l"(p));
    return a;
}
__device__ __forceinline__ uint32_t f2tf32(float f) {
    uint32_t u;
    asm("cvt.rna.tf32.f32 %0, %1;" : "=r"(u) : "f"(f));
    return u;
}
__device__ __forceinline__ float rnd_tf32(float f) {
    return __uint_as_float(f2tf32(f));
}
__device__ __forceinline__ void mma_tf32(float* c, const uint32_t* a, const uint32_t* b) {
    asm volatile(
        "mma.sync.aligned.m16n8k8.row.col.f32.tf32.tf32.f32 "
        "{%0,%1,%2,%3},{%4,%5,%6,%7},{%8,%9},{%0,%1,%2,%3};"
        : "+f"(c[0]), "+f"(c[1]), "+f"(c[2]), "+f"(c[3])
        : "r"(a[0]), "r"(a[1]), "r"(a[2]), "r"(a[3]), "r"(b[0]), "r"(b[1]));
}
__device__ __forceinline__ void ldmatrix_x4(uint32_t* r, uint32_t addr) {
    asm volatile("ldmatrix.sync.aligned.m8n8.x4.shared.b16 {%0,%1,%2,%3}, [%4];"
                 : "=r"(r[0]), "=r"(r[1]), "=r"(r[2]), "=r"(r[3]) : "r"(addr));
}
__device__ __forceinline__ void cp_async16(uint32_t saddr, const void* gaddr) {
    asm volatile("cp.async.cg.shared.global [%0], [%1], 16;"
                 :: "r"(saddr), "l"(gaddr) : "memory");
}
#define CP_COMMIT() asm volatile("cp.async.commit_group;" ::: "memory")
#define CP_WAIT2()  asm volatile("cp.async.wait_group 2;" ::: "memory")

// smem word index for (row m, k-word k) within a 128x16-word operand tile.
// XOR swizzle: conflict-free for 16B cp.async stores and all ldmatrix groups.
#define SW_WORD(m, k) ((uint32_t)(m) * 16u + ((uint32_t)(k) ^ (((((uint32_t)(m)) >> 1) & 3u) << 2)))

#define STAGE_BYTES 16384u
#define GEMM_SMEM_BYTES 65536u
#define CTX_SMEM_BYTES 66560u

// Per-thread ldmatrix address prep.
// A x4 (per mi): matrices = {rows +0/+8} x {kseg, kseg+4}
//   lane -> row = base + (lane&7) + ((lane>>3)&1)*8 ; kseg = (lane>>4)*4
// B x4 (per nj-PAIR p -> nj = 2p, 2p+1): matrices = {nj0 kseg0, nj0 kseg4, nj1 kseg0, nj1 kseg4}
//   lane -> row = base + (lane&7) + ((lane>>4)&1)*8 ; kseg = ((lane>>3)&1)*4
#define LDM_PREP()                                                              \
    uint32_t aBaseW[4], aXorW[4];                                               \
    _Pragma("unroll")                                                           \
    for (int mi = 0; mi < 4; mi++) {                                            \
        const int rowa = warp_m * 64 + mi * 16 + (lane & 7) + ((lane >> 3) & 1) * 8; \
        aBaseW[mi] = (uint32_t)rowa * 16u;                                      \
        aXorW[mi]  = (((uint32_t)rowa >> 1) & 3u) << 2;                         \
    }                                                                           \
    const uint32_t aKsel = ((uint32_t)lane >> 4) * 4u;                          \
    uint32_t bBaseW[2], bXorW[2];                                               \
    _Pragma("unroll")                                                           \
    for (int p = 0; p < 2; p++) {                                               \
        const int rowb = warp_n * 32 + p * 16 + (lane & 7) + ((lane >> 4) & 1) * 8; \
        bBaseW[p] = (uint32_t)rowb * 16u;                                       \
        bXorW[p]  = (((uint32_t)rowb >> 1) & 3u) << 2;                          \
    }                                                                           \
    const uint32_t bKsel = (((uint32_t)lane >> 3) & 1u) * 4u;

// ============================================================================
// Generic batched TF32 GEMM (cp.async 4-stage, ldmatrix-x4 fragments).
// All operands are pre-rounded to tf32 in memory: fragment path is cvt-free.
//   C = alpha * A @ B^T + bias
// ============================================================================
template <bool HAS_BIAS, bool STATS, bool ROUND_OUT>
__global__ __launch_bounds__(256, 2) void gemm_cp_kernel(
    const float* __restrict__ A, const float* __restrict__ B,
    const float* __restrict__ bias, float* __restrict__ C,
    int K, int lda, int ldb, int ldc, float alpha,
    int Hdiv,
    long long sAb, long long sAh,
    long long sBb, long long sBh,
    long long sCb, long long sCh,
    float* __restrict__ statsM, float* __restrict__ statsS)
{
    extern __shared__ char smem[];
    const uint32_t sb = smem_u32(smem);

    const int z  = blockIdx.z;
    const int zb = z / Hdiv;
    const int zh = z % Hdiv;
    A += zb * sAb + zh * sAh;
    B += zb * sBb + zh * sBh;
    C += zb * sCb + zh * sCh;

    const int tid  = threadIdx.x;
    const int wid  = tid >> 5;
    const int lane = tid & 31;
    const int m0   = blockIdx.y * 128;
    const int n0   = blockIdx.x * 128;
    const int warp_m = wid >> 2;
    const int warp_n = wid & 3;
    const int grp  = lane >> 2;
    const int tig  = lane & 3;

    const int lm = tid >> 2;
    const int lc = (tid & 3) * 4;

    LDM_PREP()

    float acc[4][4][4];
#pragma unroll
    for (int i = 0; i < 4; i++)
#pragma unroll
        for (int j = 0; j < 4; j++)
#pragma unroll
            for (int q = 0; q < 4; q++) acc[i][j][q] = 0.0f;

#define ISSUE_BODY(bufi, k0)                                                    \
    {                                                                           \
        const uint32_t ab = sb + (uint32_t)(bufi) * STAGE_BYTES;                \
        const uint32_t bbs = ab + 8192u;                                        \
        _Pragma("unroll")                                                       \
        for (int i = 0; i < 2; i++) {                                           \
            const int m = lm + i * 64;                                          \
            cp_async16(ab + SW_WORD(m, lc) * 4u,                                \
                       A + (long long)(m0 + m) * lda + (k0) + lc);              \
            cp_async16(bbs + SW_WORD(m, lc) * 4u,                               \
                       B + (long long)(n0 + m) * ldb + (k0) + lc);              \
        }                                                                       \
    }

#define COMPUTE(bufi)                                                           \
    {                                                                           \
        const uint32_t abuf = sb + (uint32_t)(bufi) * STAGE_BYTES;              \
        const uint32_t bbuf = abuf + 8192u;                                     \
        _Pragma("unroll")                                                       \
        for (int ks = 0; ks < 2; ks++) {                                        \
            const uint32_t kb = ks * 8;                                         \
            uint32_t af[4][4], bf[2][4];                                        \
            _Pragma("unroll")                                                   \
            for (int mi = 0; mi < 4; mi++) {                                    \
                const uint32_t kw = kb + aKsel;                                 \
                ldmatrix_x4(af[mi], abuf + (aBaseW[mi] + (kw ^ aXorW[mi])) * 4u); \
            }                                                                   \
            _Pragma("unroll")                                                   \
            for (int p = 0; p < 2; p++) {                                       \
                const uint32_t kw = kb + bKsel;                                 \
                ldmatrix_x4(bf[p], bbuf + (bBaseW[p] + (kw ^ bXorW[p])) * 4u);  \
            }                                                                   \
            _Pragma("unroll")                                                   \
            for (int mi = 0; mi < 4; mi++)                                      \
                _Pragma("unroll")                                               \
                for (int nj = 0; nj < 4; nj++)                                  \
                    mma_tf32(acc[mi][nj], af[mi], &bf[nj >> 1][(nj & 1) * 2]);  \
        }                                                                       \
    }

    const int S = K >> 4;

    ISSUE_BODY(0, 0)   CP_COMMIT();
    ISSUE_BODY(1, 16)  CP_COMMIT();
    ISSUE_BODY(2, 32)  CP_COMMIT();

    for (int s = 0; s < S; s++) {
        CP_WAIT2();
        __syncthreads();
        COMPUTE(s & 3)
        if (s + 3 < S) {
            ISSUE_BODY((s + 3) & 3, (s + 3) * 16)
        }
        CP_COMMIT();   // unconditional: exact wait_group accounting in the tail
    }

    // ---- write C ----
#pragma unroll
    for (int nj = 0; nj < 4; nj++) {
        const int cc = n0 + warp_n * 32 + nj * 8 + tig * 2;
        float b0 = 0.0f, b1 = 0.0f;
        if (HAS_BIAS) { b0 = bias[cc]; b1 = bias[cc + 1]; }
#pragma unroll
        for (int mi = 0; mi < 4; mi++) {
            const long long r0 = m0 + warp_m * 64 + mi * 16 + grp;
            const long long r1 = r0 + 8;
            float2 v0, v1;
            v0.x = alpha * acc[mi][nj][0] + b0;
            v0.y = alpha * acc[mi][nj][1] + b1;
            v1.x = alpha * acc[mi][nj][2] + b0;
            v1.y = alpha * acc[mi][nj][3] + b1;
            if (ROUND_OUT) {
                v0.x = rnd_tf32(v0.x); v0.y = rnd_tf32(v0.y);
                v1.x = rnd_tf32(v1.x); v1.y = rnd_tf32(v1.y);
            }
            *reinterpret_cast<float2*>(C + r0 * ldc + cc) = v0;
            *reinterpret_cast<float2*>(C + r1 * ldc + cc) = v1;
        }
    }

    // ---- per-tile softmax stats (scores only) ----
    if (STATS) {
        __syncthreads();
        float* sred    = reinterpret_cast<float*>(smem);          // [4][128]
        float* rowmaxs = reinterpret_cast<float*>(smem) + 512;    // [128]

#pragma unroll
        for (int mi = 0; mi < 4; mi++) {
#pragma unroll
            for (int h = 0; h < 2; h++) {
                float mx = -1e30f;
#pragma unroll
                for (int nj = 0; nj < 4; nj++)
                    mx = fmaxf(mx, fmaxf(alpha * acc[mi][nj][h * 2],
                                         alpha * acc[mi][nj][h * 2 + 1]));
                mx = fmaxf(mx, __shfl_xor_sync(0xffffffffu, mx, 1));
                mx = fmaxf(mx, __shfl_xor_sync(0xffffffffu, mx, 2));
                const int rl = warp_m * 64 + mi * 16 + grp + h * 8;
                if (tig == 0) sred[warp_n * 128 + rl] = mx;
            }
        }
        __syncthreads();
        if (tid < 128) {
            float rm = fmaxf(fmaxf(sred[tid], sred[128 + tid]),
                             fmaxf(sred[256 + tid], sred[384 + tid]));
            rowmaxs[tid] = rm;
        }
        __syncthreads();

#pragma unroll
        for (int mi = 0; mi < 4; mi++) {
#pragma unroll
            for (int h = 0; h < 2; h++) {
                const int rl = warp_m * 64 + mi * 16 + grp + h * 8;
                const float rm = rowmaxs[rl];
                float s = 0.0f;
#pragma unroll
                for (int nj = 0; nj < 4; nj++) {
                    s += __expf(alpha * acc[mi][nj][h * 2]     - rm);
                    s += __expf(alpha * acc[mi][nj][h * 2 + 1] - rm);
                }
                s += __shfl_xor_sync(0xffffffffu, s, 1);
                s += __shfl_xor_sync(0xffffffffu, s, 2);
                if (tig == 0) sred[warp_n * 128 + rl] = s;
            }
        }
        __syncthreads();
        if (tid < 128) {
            const float sg = sred[tid] + sred[128 + tid] + sred[256 + tid] + sred[384 + tid];
            const long long gi = ((long long)z * SS + m0 + tid) * NTILE + blockIdx.x;
            statsM[gi] = rowmaxs[tid];
            statsS[gi] = sg;
        }
    }
#undef ISSUE_BODY
#undef COMPUTE
}

// ============================================================================
// Round weight matrices to tf32 (prepass). grid.z selects the matrix.
// ============================================================================
__global__ __launch_bounds__(256) void round_weights_kernel(
    const float* __restrict__ w0, const float* __restrict__ w1,
    const float* __restrict__ w2, const float* __restrict__ w3,
    float* __restrict__ dst)
{
    const float* src = (blockIdx.z == 0) ? w0 : (blockIdx.z == 1) ? w1
                     : (blockIdx.z == 2) ? w2 : w3;
    float* d = dst + (size_t)blockIdx.z * DMODEL * DMODEL;
    const long long i = ((long long)blockIdx.x * 256 + threadIdx.x) * 4;
    float4 v = *reinterpret_cast<const float4*>(src + i);
    v.x = rnd_tf32(v.x); v.y = rnd_tf32(v.y);
    v.z = rnd_tf32(v.z); v.w = rnd_tf32(v.w);
    *reinterpret_cast<float4*>(d + i) = v;
}

// ============================================================================
// Round input tensors Q,K,V to tf32 (prepass). grid.z selects the tensor.
// ============================================================================
__global__ __launch_bounds__(256) void round_inputs_kernel(
    const float* __restrict__ x0, const float* __restrict__ x1,
    const float* __restrict__ x2, float* __restrict__ dst)
{
    const float* src = (blockIdx.z == 0) ? x0 : (blockIdx.z == 1) ? x1 : x2;
    float* d = dst + (size_t)blockIdx.z * BB * SS * DMODEL;
    const long long i = ((long long)blockIdx.x * 256 + threadIdx.x) * 4;
    float4 v = *reinterpret_cast<const float4*>(src + i);
    v.x = rnd_tf32(v.x); v.y = rnd_tf32(v.y);
    v.z = rnd_tf32(v.z); v.w = rnd_tf32(v.w);
    *reinterpret_cast<float4*>(d + i) = v;
}

// ============================================================================
// Combine per-tile stats into global row max + inverse sum.
// ============================================================================
__global__ __launch_bounds__(256) void combine_stats_kernel(
    const float* __restrict__ sM, const float* __restrict__ sS,
    float* __restrict__ rowM, float* __restrict__ rowInv)
{
    const long long r = (long long)blockIdx.x * 256 + threadIdx.x;
    const float* pm = sM + r * NTILE;
    const float* ps = sS + r * NTILE;
    float M = -1e30f;
#pragma unroll
    for (int t = 0; t < NTILE; t++) M = fmaxf(M, pm[t]);
    float S = 0.0f;
#pragma unroll
    for (int t = 0; t < NTILE; t++) S += ps[t] * __expf(pm[t] - M);
    rowM[r]   = M;
    rowInv[r] = 1.0f / S;
}

// ============================================================================
// Fused softmax + ctx GEMM (ldmatrix-x4 fragments, cvt-free).
// ============================================================================
__global__ __launch_bounds__(256, 2) void ctx_fused_kernel(
    const float* __restrict__ RAW, const float* __restrict__ VT,
    float* __restrict__ CTX, float* __restrict__ ATTN,
    const float* __restrict__ rowM, const float* __restrict__ rowInv)
{
    extern __shared__ char smem[];
    const uint32_t sb = smem_u32(smem);
    float* sM_s = reinterpret_cast<float*>(smem + GEMM_SMEM_BYTES);
    float* sI_s = sM_s + 128;

    const int z  = blockIdx.z;
    const int zb = z >> 3;
    const int zh = z & 7;
    const float* A = RAW + (long long)z * SS * SS;
    const float* B = VT + (long long)z * DK * SS;
    float* C = CTX + (long long)zb * SS * DMODEL + (long long)zh * DK;
    float* AT = ATTN + (long long)z * SS * SS;

    const int tid  = threadIdx.x;
    const int wid  = tid >> 5;
    const int lane = tid & 31;
    const int m0   = blockIdx.y * 128;
    const int warp_m = wid >> 2;
    const int warp_n = wid & 3;
    const int grp  = lane >> 2;
    const int tig  = lane & 3;

    const int lm = tid >> 2;
    const int lc = (tid & 3) * 4;

    LDM_PREP()

    if (tid < 128) {
        sM_s[tid] = rowM[(long long)z * SS + m0 + tid];
        sI_s[tid] = rowInv[(long long)z * SS + m0 + tid];
    }

    float acc[4][4][4];
#pragma unroll
    for (int i = 0; i < 4; i++)
#pragma unroll
        for (int j = 0; j < 4; j++)
#pragma unroll
            for (int q = 0; q < 4; q++) acc[i][j][q] = 0.0f;

#define ISSUE_BODY(bufi, k0)                                                    \
    {                                                                           \
        const uint32_t ab = sb + (uint32_t)(bufi) * STAGE_BYTES;                \
        const uint32_t bbs = ab + 8192u;                                        \
        _Pragma("unroll")                                                       \
        for (int i = 0; i < 2; i++) {                                           \
            const int m = lm + i * 64;                                          \
            cp_async16(ab + SW_WORD(m, lc) * 4u,                                \
                       A + (long long)(m0 + m) * SS + (k0) + lc);               \
            cp_async16(bbs + SW_WORD(m, lc) * 4u,                               \
                       B + (long long)m * SS + (k0) + lc);                      \
        }                                                                       \
    }

#define TRANSFORM(bufi, k0)                                                     \
    {                                                                           \
        float* ab = reinterpret_cast<float*>(smem + (uint32_t)(bufi) * STAGE_BYTES); \
        _Pragma("unroll")                                                       \
        for (int i = 0; i < 2; i++) {                                           \
            const int m = (tid >> 2) + i * 64;                                  \
            const int kg = (tid & 3) * 4;                                       \
            const float rm = sM_s[m], ri = sI_s[m];                             \
            float4* p = reinterpret_cast<float4*>(&ab[SW_WORD(m, kg)]);         \
            float4 v = *p;                                                      \
            v.x = __expf(v.x - rm) * ri;                                        \
            v.y = __expf(v.y - rm) * ri;                                        \
            v.z = __expf(v.z - rm) * ri;                                        \
            v.w = __expf(v.w - rm) * ri;                                        \
            *reinterpret_cast<float4*>(AT + (long long)(m0 + m) * SS + (k0) + kg) = v; \
            float4 r4;                                                          \
            r4.x = rnd_tf32(v.x); r4.y = rnd_tf32(v.y);                         \
            r4.z = rnd_tf32(v.z); r4.w = rnd_tf32(v.w);                         \
            *p = r4;                                                            \
        }                                                                       \
    }

#define COMPUTE(bufi)                                                           \
    {                                                                           \
        const uint32_t abuf = sb + (uint32_t)(bufi) * STAGE_BYTES;              \
        const uint32_t bbuf = abuf + 8192u;                                     \
        _Pragma("unroll")                                                       \
        for (int ks = 0; ks < 2; ks++) {                                        \
            const uint32_t kb = ks * 8;                                         \
            uint32_t af[4][4], bf[2][4];                                        \
            _Pragma("unroll")                                                   \
            for (int mi = 0; mi < 4; mi++) {                                    \
                const uint32_t kw = kb + aKsel;                                 \
                ldmatrix_x4(af[mi], abuf + (aBaseW[mi] + (kw ^ aXorW[mi])) * 4u); \
            }                                                                   \
            _Pragma("unroll")                                                   \
            for (int p = 0; p < 2; p++) {                                       \
                const uint32_t kw = kb + bKsel;                                 \
                ldmatrix_x4(bf[p], bbuf + (bBaseW[p] + (kw ^ bXorW[p])) * 4u);  \
            }                                                                   \
            _Pragma("unroll")                                                   \
            for (int mi = 0; mi < 4; mi++)                                      \
                _Pragma("unroll")                                               \
                for (int nj = 0; nj < 4; nj++)                                  \
                    mma_tf32(acc[mi][nj], af[mi], &bf[nj >> 1][(nj & 1) * 2]);  \
        }                                                                       \
    }

    const int S = SS >> 4;   // 128 stages

    ISSUE_BODY(0, 0)   CP_COMMIT();
    ISSUE_BODY(1, 16)  CP_COMMIT();
    ISSUE_BODY(2, 32)  CP_COMMIT();

    for (int s = 0; s < S; s++) {
        CP_WAIT2();
        __syncthreads();
        TRANSFORM(s & 3, s * 16)
        __syncthreads();
        COMPUTE(s & 3)
        if (s + 3 < S) {
            ISSUE_BODY((s + 3) & 3, (s + 3) * 16)
        }
        CP_COMMIT();
    }

    // ---- write ctx (tf32-rounded: feeds out-projection) ----
#pragma unroll
    for (int nj = 0; nj < 4; nj++) {
        const int cc = warp_n * 32 + nj * 8 + tig * 2;
#pragma unroll
        for (int mi = 0; mi < 4; mi++) {
            const long long r0 = m0 + warp_m * 64 + mi * 16 + grp;
            const long long r1 = r0 + 8;
            float2 v0, v1;
            v0.x = rnd_tf32(acc[mi][nj][0]);
            v0.y = rnd_tf32(acc[mi][nj][1]);
            v1.x = rnd_tf32(acc[mi][nj][2]);
            v1.y = rnd_tf32(acc[mi][nj][3]);
            *reinterpret_cast<float2*>(C + r0 * DMODEL + cc) = v0;
            *reinterpret_cast<float2*>(C + r1 * DMODEL + cc) = v1;
        }
    }
#undef ISSUE_BODY
#undef TRANSFORM
#undef COMPUTE
}

// ----------------------------------------------------------------------------
// V transpose: g_v [(b*S+s)][h*128+n]  ->  g_vt [((b*8+h)*128+n)][s]
// ----------------------------------------------------------------------------
__global__ void transpose_v_kernel(const float* __restrict__ v, float* __restrict__ vt)
{
    __shared__ float t[32][33];
    const int z = blockIdx.z, b = z >> 3, h = z & 7;
    const int s0 = blockIdx.x * 32, n0 = blockIdx.y * 32;
    const int tx = threadIdx.x, ty = threadIdx.y;
#pragma unroll
    for (int j = ty; j < 32; j += 8)
        t[j][tx] = v[((long long)b * SS + s0 + j) * DMODEL + h * DK + n0 + tx];
    __syncthreads();
#pragma unroll
    for (int j = ty; j < 32; j += 8)
        vt[((long long)z * DK + n0 + j) * SS + s0 + tx] = t[tx][j];
}

extern "C" void kernel_launch(void* const* d_in, const int* in_sizes, int n_in,
                              void* d_out, int out_size)
{
    const float* Q  = (const float*)d_in[0];
    const float* K  = (const float*)d_in[1];
    const float* V  = (const float*)d_in[2];
    const float* Wq = (const float*)d_in[3];
    const float* bq = (const float*)d_in[4];
    const float* Wk = (const float*)d_in[5];
    const float* bk = (const float*)d_in[6];
    const float* Wv = (const float*)d_in[7];
    const float* bv = (const float*)d_in[8];
    const float* Wo = (const float*)d_in[9];
    const float* bo = (const float*)d_in[10];

    float* out = (float*)d_out;

    const long long OUT_ELEMS  = (long long)BB * SS * DMODEL;
    const long long ATTN_ELEMS = (long long)NZ * SS * SS;

    float *qp, *kp, *vp, *vtp, *ctxp, *rawp, *sMp, *sSp, *rMp, *rIp, *wp, *inp;
    cudaGetSymbolAddress((void**)&qp,   g_q);
    cudaGetSymbolAddress((void**)&kp,   g_k);
    cudaGetSymbolAddress((void**)&vp,   g_v);
    cudaGetSymbolAddress((void**)&vtp,  g_vt);
    cudaGetSymbolAddress((void**)&ctxp, g_ctx);
    cudaGetSymbolAddress((void**)&rawp, g_raw);
    cudaGetSymbolAddress((void**)&sMp,  g_statsM);
    cudaGetSymbolAddress((void**)&sSp,  g_statsS);
    cudaGetSymbolAddress((void**)&rMp,  g_rowM);
    cudaGetSymbolAddress((void**)&rIp,  g_rowInv);
    cudaGetSymbolAddress((void**)&wp,   g_w);
    cudaGetSymbolAddress((void**)&inp,  g_in);

    float* attn = ((long long)out_size >= OUT_ELEMS + ATTN_ELEMS)
                      ? (out + OUT_ELEMS) : rawp;

    // GEMM variants: <HAS_BIAS, STATS, ROUND_OUT> (all operands pre-rounded)
    auto projK  = gemm_cp_kernel<true,  false, true >;
    auto scoreK = gemm_cp_kernel<false, true,  false>;
    auto outK   = gemm_cp_kernel<true,  false, false>;
    cudaFuncSetAttribute(projK,  cudaFuncAttributeMaxDynamicSharedMemorySize, GEMM_SMEM_BYTES);
    cudaFuncSetAttribute(scoreK, cudaFuncAttributeMaxDynamicSharedMemorySize, GEMM_SMEM_BYTES);
    cudaFuncSetAttribute(outK,   cudaFuncAttributeMaxDynamicSharedMemorySize, GEMM_SMEM_BYTES);
    cudaFuncSetAttribute(ctx_fused_kernel,
                         cudaFuncAttributeMaxDynamicSharedMemorySize, CTX_SMEM_BYTES);

    const int M = BB * SS;
    const float inv_sqrt_dk = 0.08838834764831845f;

    dim3 blk(256);

    // 0) prepass: round weights + inputs to tf32
    {
        dim3 gW(DMODEL * DMODEL / (256 * 4), 1, 4);
        round_weights_kernel<<<gW, blk>>>(Wq, Wk, Wv, Wo, wp);
        dim3 gI((BB * SS * DMODEL) / (256 * 4), 1, 3);
        round_inputs_kernel<<<gI, blk>>>(Q, K, V, inp);
    }
    float* wq = wp;
    float* wk = wp + (size_t)DMODEL * DMODEL;
    float* wv = wp + 2 * (size_t)DMODEL * DMODEL;
    float* wo = wp + 3 * (size_t)DMODEL * DMODEL;
    float* qin = inp;
    float* kin = inp + (size_t)BB * SS * DMODEL;
    float* vin = inp + 2 * (size_t)BB * SS * DMODEL;

    // 1-3) projections: X @ W^T + b (outputs tf32-rounded)
    dim3 gProj(DMODEL / 128, M / 128, 1);
    projK<<<gProj, blk, GEMM_SMEM_BYTES>>>(qin, wq, bq, qp,
        DMODEL, DMODEL, DMODEL, DMODEL, 1.0f, 1, 0, 0, 0, 0, 0, 0, nullptr, nullptr);
    projK<<<gProj, blk, GEMM_SMEM_BYTES>>>(kin, wk, bk, kp,
        DMODEL, DMODEL, DMODEL, DMODEL, 1.0f, 1, 0, 0, 0, 0, 0, 0, nullptr, nullptr);
    projK<<<gProj, blk, GEMM_SMEM_BYTES>>>(vin, wv, bv, vp,
        DMODEL, DMODEL, DMODEL, DMODEL, 1.0f, 1, 0, 0, 0, 0, 0, 0, nullptr, nullptr);

    // 3b) transpose V per head
    {
        dim3 gT(SS / 32, DK / 32, NZ);
        dim3 bT(32, 8);
        transpose_v_kernel<<<gT, bT>>>(vp, vtp);
    }

    // 4) raw scores + per-tile softmax stats
    dim3 gScores(SS / 128, SS / 128, NZ);
    scoreK<<<gScores, blk, GEMM_SMEM_BYTES>>>(qp, kp, nullptr, rawp,
        DK, DMODEL, DMODEL, SS, inv_sqrt_dk,
        NHEADS,
        (long long)SS * DMODEL, (long long)DK,
        (long long)SS * DMODEL, (long long)DK,
        (long long)NHEADS * SS * SS, (long long)SS * SS,
        sMp, sSp);

    // 5) combine stats
    combine_stats_kernel<<<(NZ * SS) / 256, blk>>>(sMp, sSp, rMp, rIp);

    // 6) fused softmax + ctx GEMM (+ attn output write)
    {
        dim3 gCtx(1, SS / 128, NZ);
        ctx_fused_kernel<<<gCtx, blk, CTX_SMEM_BYTES>>>(rawp, vtp, ctxp, attn, rMp, rIp);
    }

    // 7) out = ctx @ Wo^T + bo
    outK<<<gProj, blk, GEMM_SMEM_BYTES>>>(ctxp, wo, bo, out,
        DMODEL, DMODEL, DMODEL, DMODEL, 1.0f, 1, 0, 0, 0, 0, 0, 0, nullptr, nullptr);
}

// round 12
// speedup vs baseline: 1.2157x; 1.2157x over previous
#include <cuda_runtime.h>
#include <cuda_fp16.h>
#include <math.h>
#include <stdint.h>

#define DMODEL 1024
#define NHEADS 8
#define DK 128
#define BB 2
#define SS 2048
#define NZ (BB * NHEADS)          // 16
#define NTILE (SS / 128)          // 16

// Scratch (allocation-free rule: __device__ globals)
__device__ __half g_q[(size_t)BB * SS * DMODEL];
__device__ __half g_k[(size_t)BB * SS * DMODEL];
__device__ __half g_v[(size_t)BB * SS * DMODEL];
__device__ __half g_vt[(size_t)BB * NHEADS * DK * SS];
__device__ __half g_ctx[(size_t)BB * SS * DMODEL];
__device__ float  g_raw[(size_t)NZ * SS * SS];          // raw scores stay fp32
__device__ float  g_statsM[(size_t)NZ * SS * NTILE];
__device__ float  g_statsS[(size_t)NZ * SS * NTILE];
__device__ float  g_rowM[(size_t)NZ * SS];
__device__ float  g_rowInv[(size_t)NZ * SS];
__device__ __half g_w[4][(size_t)DMODEL * DMODEL];      // fp16 weights
__device__ __half g_in[3][(size_t)BB * SS * DMODEL];    // fp16 Q,K,V inputs

__device__ __forceinline__ uint32_t smem_u32(const void* p) {
    uint32_t a;
    asm("{ .reg .u64 t; cvta.to.shared.u64 t, %1; cvt.u32.u64 %0, t; }" : "=r"(a) : "l"(p));
    return a;
}
__device__ __forceinline__ void mma_fp16(float* c, const uint32_t* a, const uint32_t* b) {
    asm volatile(
        "mma.sync.aligned.m16n8k16.row.col.f32.f16.f16.f32 "
        "{%0,%1,%2,%3},{%4,%5,%6,%7},{%8,%9},{%0,%1,%2,%3};"
        : "+f"(c[0]), "+f"(c[1]), "+f"(c[2]), "+f"(c[3])
        : "r"(a[0]), "r"(a[1]), "r"(a[2]), "r"(a[3]), "r"(b[0]), "r"(b[1]));
}
__device__ __forceinline__ void ldmatrix_x4(uint32_t* r, uint32_t addr) {
    asm volatile("ldmatrix.sync.aligned.m8n8.x4.shared.b16 {%0,%1,%2,%3}, [%4];"
                 : "=r"(r[0]), "=r"(r[1]), "=r"(r[2]), "=r"(r[3]) : "r"(addr));
}
__device__ __forceinline__ void cp_async16(uint32_t saddr, const void* gaddr) {
    asm volatile("cp.async.cg.shared.global [%0], [%1], 16;"
                 :: "r"(saddr), "l"(gaddr) : "memory");
}
#define CP_COMMIT() asm volatile("cp.async.commit_group;" ::: "memory")
#define CP_WAIT2()  asm volatile("cp.async.wait_group 2;" ::: "memory")
#define CP_WAIT1()  asm volatile("cp.async.wait_group 1;" ::: "memory")

__device__ __forceinline__ uint32_t pack_h2(float lo, float hi) {
    __half2 h = __floats2half2_rn(lo, hi);
    return *reinterpret_cast<uint32_t*>(&h);
}

// smem word index for (row m, k-word k) within a 128-row x 16-word tile
// (16 words = 32 halves per row). Conflict-free for 16B cp.async stores and
// all ldmatrix 8-lane groups.
#define SW_WORD(m, k) ((uint32_t)(m) * 16u + ((uint32_t)(k) ^ (((((uint32_t)(m)) >> 1) & 3u) << 2)))

#define STAGE_BYTES 16384u        // A(8KB fp16) + B(8KB fp16), 32 halves of k
#define GEMM_SMEM_BYTES 65536u    // 4 stages

// ctx stages: raw fp32 (16KB) + p fp16 (8KB) + vt fp16 (8KB) = 32KB, 3-stage ring
#define CTX_STAGE 32768u
#define CTX_SMEM_BYTES (3 * CTX_STAGE + 1024)   // + rowM/rowInv cache

// ldmatrix address prep (identical geometry for f16 m16n8k16 fragments).
#define LDM_PREP()                                                              \
    uint32_t aBaseW[4], aXorW[4];                                               \
    _Pragma("unroll")                                                           \
    for (int mi = 0; mi < 4; mi++) {                                            \
        const int rowa = warp_m * 64 + mi * 16 + (lane & 7) + ((lane >> 3) & 1) * 8; \
        aBaseW[mi] = (uint32_t)rowa * 16u;                                      \
        aXorW[mi]  = (((uint32_t)rowa >> 1) & 3u) << 2;                         \
    }                                                                           \
    const uint32_t aKsel = ((uint32_t)lane >> 4) * 4u;                          \
    uint32_t bBaseW[2], bXorW[2];                                               \
    _Pragma("unroll")                                                           \
    for (int p = 0; p < 2; p++) {                                               \
        const int rowb = warp_n * 32 + p * 16 + (lane & 7) + ((lane >> 4) & 1) * 8; \
        bBaseW[p] = (uint32_t)rowb * 16u;                                       \
        bXorW[p]  = (((uint32_t)rowb >> 1) & 3u) << 2;                          \
    }                                                                           \
    const uint32_t bKsel = (((uint32_t)lane >> 3) & 1u) * 4u;

// Shared COMPUTE over one 32-half k-stage: 2 x k16 steps.
#define COMPUTE_FP16(abufAddr, bbufAddr)                                        \
    {                                                                           \
        _Pragma("unroll")                                                       \
        for (int ks = 0; ks < 2; ks++) {                                        \
            const uint32_t kb = ks * 8;                                         \
            uint32_t af[4][4], bf[2][4];                                        \
            _Pragma("unroll")                                                   \
            for (int mi = 0; mi < 4; mi++) {                                    \
                const uint32_t kw = kb + aKsel;                                 \
                ldmatrix_x4(af[mi], (abufAddr) + (aBaseW[mi] + (kw ^ aXorW[mi])) * 4u); \
            }                                                                   \
            _Pragma("unroll")                                                   \
            for (int p = 0; p < 2; p++) {                                       \
                const uint32_t kw = kb + bKsel;                                 \
                ldmatrix_x4(bf[p], (bbufAddr) + (bBaseW[p] + (kw ^ bXorW[p])) * 4u); \
            }                                                                   \
            _Pragma("unroll")                                                   \
            for (int mi = 0; mi < 4; mi++)                                      \
                _Pragma("unroll")                                               \
                for (int nj = 0; nj < 4; nj++)                                  \
                    mma_fp16(acc[mi][nj], af[mi], &bf[nj >> 1][(nj & 1) * 2]);  \
        }                                                                       \
    }

// ============================================================================
// Batched FP16 GEMM (cp.async 4-stage):  C = alpha * A @ B^T + bias
//   A: [M,K] halves row-major (lda halves).  B: [N,K] halves.
//   OUT_HALF: write C as __half (else float). STATS: softmax row stats.
//   K % 32 == 0, K >= 64.
// ============================================================================
template <bool HAS_BIAS, bool STATS, bool OUT_HALF>
__global__ __launch_bounds__(256, 2) void gemm_fp16_kernel(
    const __half* __restrict__ A, const __half* __restrict__ B,
    const float* __restrict__ bias, void* __restrict__ Cv,
    int K, int lda, int ldb, int ldc, float alpha,
    int Hdiv,
    long long sAb, long long sAh,
    long long sBb, long long sBh,
    long long sCb, long long sCh,
    float* __restrict__ statsM, float* __restrict__ statsS)
{
    extern __shared__ char smem[];
    const uint32_t sb = smem_u32(smem);

    const int z  = blockIdx.z;
    const int zb = z / Hdiv;
    const int zh = z % Hdiv;
    A += zb * sAb + zh * sAh;
    B += zb * sBb + zh * sBh;
    const long long coff = zb * sCb + zh * sCh;

    const int tid  = threadIdx.x;
    const int wid  = tid >> 5;
    const int lane = tid & 31;
    const int m0   = blockIdx.y * 128;
    const int n0   = blockIdx.x * 128;
    const int warp_m = wid >> 2;
    const int warp_n = wid & 3;
    const int grp  = lane >> 2;
    const int tig  = lane & 3;

    const int lm  = tid >> 2;          // 0..63
    const int lcw = (tid & 3) * 4;     // word col
    const int lch = (tid & 3) * 8;     // halves col

    LDM_PREP()

    float acc[4][4][4];
#pragma unroll
    for (int i = 0; i < 4; i++)
#pragma unroll
        for (int j = 0; j < 4; j++)
#pragma unroll
            for (int q = 0; q < 4; q++) acc[i][j][q] = 0.0f;

#define ISSUE_BODY(bufi, k0)                                                    \
    {                                                                           \
        const uint32_t ab = sb + (uint32_t)(bufi) * STAGE_BYTES;                \
        const uint32_t bbs = ab + 8192u;                                        \
        _Pragma("unroll")                                                       \
        for (int i = 0; i < 2; i++) {                                           \
            const int m = lm + i * 64;                                          \
            cp_async16(ab + SW_WORD(m, lcw) * 4u,                               \
                       A + (long long)(m0 + m) * lda + (k0) + lch);             \
            cp_async16(bbs + SW_WORD(m, lcw) * 4u,                              \
                       B + (long long)(n0 + m) * ldb + (k0) + lch);             \
        }                                                                       \
    }

    const int S = K >> 5;   // stages of 32 halves

    ISSUE_BODY(0, 0)   CP_COMMIT();
    ISSUE_BODY(1, 32)  CP_COMMIT();
    ISSUE_BODY(2, 64)  CP_COMMIT();

    for (int s = 0; s < S; s++) {
        CP_WAIT2();
        __syncthreads();
        {
            const uint32_t abuf = sb + (uint32_t)(s & 3) * STAGE_BYTES;
            const uint32_t bbuf = abuf + 8192u;
            COMPUTE_FP16(abuf, bbuf)
        }
        if (s + 3 < S) {
            ISSUE_BODY((s + 3) & 3, (s + 3) * 32)
        }
        CP_COMMIT();   // unconditional: exact wait_group accounting in the tail
    }

    // ---- write C ----
#pragma unroll
    for (int nj = 0; nj < 4; nj++) {
        const int cc = n0 + warp_n * 32 + nj * 8 + tig * 2;
        float b0 = 0.0f, b1 = 0.0f;
        if (HAS_BIAS) { b0 = bias[cc]; b1 = bias[cc + 1]; }
#pragma unroll
        for (int mi = 0; mi < 4; mi++) {
            const long long r0 = m0 + warp_m * 64 + mi * 16 + grp;
            const long long r1 = r0 + 8;
            const float x0 = alpha * acc[mi][nj][0] + b0;
            const float x1 = alpha * acc[mi][nj][1] + b1;
            const float x2 = alpha * acc[mi][nj][2] + b0;
            const float x3 = alpha * acc[mi][nj][3] + b1;
            if (OUT_HALF) {
                __half* C = reinterpret_cast<__half*>(Cv) + coff;
                uint32_t u0 = pack_h2(x0, x1);
                uint32_t u1 = pack_h2(x2, x3);
                *reinterpret_cast<uint32_t*>(C + r0 * ldc + cc) = u0;
                *reinterpret_cast<uint32_t*>(C + r1 * ldc + cc) = u1;
            } else {
                float* C = reinterpret_cast<float*>(Cv) + coff;
                *reinterpret_cast<float2*>(C + r0 * ldc + cc) = make_float2(x0, x1);
                *reinterpret_cast<float2*>(C + r1 * ldc + cc) = make_float2(x2, x3);
            }
        }
    }

    // ---- per-tile softmax stats (scores only) ----
    if (STATS) {
        __syncthreads();
        float* sred    = reinterpret_cast<float*>(smem);          // [4][128]
        float* rowmaxs = reinterpret_cast<float*>(smem) + 512;    // [128]

#pragma unroll
        for (int mi = 0; mi < 4; mi++) {
#pragma unroll
            for (int h = 0; h < 2; h++) {
                float mx = -1e30f;
#pragma unroll
                for (int nj = 0; nj < 4; nj++)
                    mx = fmaxf(mx, fmaxf(alpha * acc[mi][nj][h * 2],
                                         alpha * acc[mi][nj][h * 2 + 1]));
                mx = fmaxf(mx, __shfl_xor_sync(0xffffffffu, mx, 1));
                mx = fmaxf(mx, __shfl_xor_sync(0xffffffffu, mx, 2));
                const int rl = warp_m * 64 + mi * 16 + grp + h * 8;
                if (tig == 0) sred[warp_n * 128 + rl] = mx;
            }
        }
        __syncthreads();
        if (tid < 128) {
            float rm = fmaxf(fmaxf(sred[tid], sred[128 + tid]),
                             fmaxf(sred[256 + tid], sred[384 + tid]));
            rowmaxs[tid] = rm;
        }
        __syncthreads();

#pragma unroll
        for (int mi = 0; mi < 4; mi++) {
#pragma unroll
            for (int h = 0; h < 2; h++) {
                const int rl = warp_m * 64 + mi * 16 + grp + h * 8;
                const float rm = rowmaxs[rl];
                float s = 0.0f;
#pragma unroll
                for (int nj = 0; nj < 4; nj++) {
                    s += __expf(alpha * acc[mi][nj][h * 2]     - rm);
                    s += __expf(alpha * acc[mi][nj][h * 2 + 1] - rm);
                }
                s += __shfl_xor_sync(0xffffffffu, s, 1);
                s += __shfl_xor_sync(0xffffffffu, s, 2);
                if (tig == 0) sred[warp_n * 128 + rl] = s;
            }
        }
        __syncthreads();
        if (tid < 128) {
            const float sg = sred[tid] + sred[128 + tid] + sred[256 + tid] + sred[384 + tid];
            const long long gi = ((long long)z * SS + m0 + tid) * NTILE + blockIdx.x;
            statsM[gi] = rowmaxs[tid];
            statsS[gi] = sg;
        }
    }
#undef ISSUE_BODY
}

// ============================================================================
// Prepass: convert fp32 tensors to fp16. grid.z selects the tensor.
// ============================================================================
__global__ __launch_bounds__(256) void cvt_weights_kernel(
    const float* __restrict__ w0, const float* __restrict__ w1,
    const float* __restrict__ w2, const float* __restrict__ w3,
    __half* __restrict__ dst)
{
    const float* src = (blockIdx.z == 0) ? w0 : (blockIdx.z == 1) ? w1
                     : (blockIdx.z == 2) ? w2 : w3;
    __half* d = dst + (size_t)blockIdx.z * DMODEL * DMODEL;
    const long long i = ((long long)blockIdx.x * 256 + threadIdx.x) * 4;
    float4 v = *reinterpret_cast<const float4*>(src + i);
    uint2 u;
    u.x = pack_h2(v.x, v.y);
    u.y = pack_h2(v.z, v.w);
    *reinterpret_cast<uint2*>(d + i) = u;
}

__global__ __launch_bounds__(256) void cvt_inputs_kernel(
    const float* __restrict__ x0, const float* __restrict__ x1,
    const float* __restrict__ x2, __half* __restrict__ dst)
{
    const float* src = (blockIdx.z == 0) ? x0 : (blockIdx.z == 1) ? x1 : x2;
    __half* d = dst + (size_t)blockIdx.z * BB * SS * DMODEL;
    const long long i = ((long long)blockIdx.x * 256 + threadIdx.x) * 4;
    float4 v = *reinterpret_cast<const float4*>(src + i);
    uint2 u;
    u.x = pack_h2(v.x, v.y);
    u.y = pack_h2(v.z, v.w);
    *reinterpret_cast<uint2*>(d + i) = u;
}

// ============================================================================
// Combine per-tile stats into global row max + inverse sum.
// ============================================================================
__global__ __launch_bounds__(256) void combine_stats_kernel(
    const float* __restrict__ sM, const float* __restrict__ sS,
    float* __restrict__ rowM, float* __restrict__ rowInv)
{
    const long long r = (long long)blockIdx.x * 256 + threadIdx.x;
    const float* pm = sM + r * NTILE;
    const float* ps = sS + r * NTILE;
    float M = -1e30f;
#pragma unroll
    for (int t = 0; t < NTILE; t++) M = fmaxf(M, pm[t]);
    float S = 0.0f;
#pragma unroll
    for (int t = 0; t < NTILE; t++) S += ps[t] * __expf(pm[t] - M);
    rowM[r]   = M;
    rowInv[r] = 1.0f / S;
}

// ============================================================================
// Fused softmax + ctx GEMM (fp16 mma). 3-stage ring:
//   per stage: raw fp32 (16KB) | p fp16 (8KB) | vt fp16 (8KB)
// Transform: p = exp(raw - M) * inv -> fp32 STG to attn, fp16 to smem p-region.
// ============================================================================
__global__ __launch_bounds__(256, 2) void ctx_fused_kernel(
    const float* __restrict__ RAW, const __half* __restrict__ VT,
    __half* __restrict__ CTX, float* __restrict__ ATTN,
    const float* __restrict__ rowM, const float* __restrict__ rowInv)
{
    extern __shared__ char smem[];
    const uint32_t sb = smem_u32(smem);
    float* sM_s = reinterpret_cast<float*>(smem + 3 * CTX_STAGE);
    float* sI_s = sM_s + 128;

    const int z  = blockIdx.z;
    const int zb = z >> 3;
    const int zh = z & 7;
    const float*  A = RAW + (long long)z * SS * SS;
    const __half* B = VT + (long long)z * DK * SS;
    __half* C = CTX + (long long)zb * SS * DMODEL + (long long)zh * DK;
    float* AT = ATTN + (long long)z * SS * SS;

    const int tid  = threadIdx.x;
    const int wid  = tid >> 5;
    const int lane = tid & 31;
    const int m0   = blockIdx.y * 128;
    const int warp_m = wid >> 2;
    const int warp_n = wid & 3;
    const int grp  = lane >> 2;
    const int tig  = lane & 3;

    LDM_PREP()

    if (tid < 128) {
        sM_s[tid] = rowM[(long long)z * SS + m0 + tid];
        sI_s[tid] = rowInv[(long long)z * SS + m0 + tid];
    }

    float acc[4][4][4];
#pragma unroll
    for (int i = 0; i < 4; i++)
#pragma unroll
        for (int j = 0; j < 4; j++)
#pragma unroll
            for (int q = 0; q < 4; q++) acc[i][j][q] = 0.0f;

    const int rm_row = tid >> 1;            // 0..127
    const int rm_sh  = (tid & 1) * 16;      // s-offset within stage (fp32)

#define ISSUE_BODY(bufi, k0)                                                    \
    {                                                                           \
        const uint32_t rawb = sb + (uint32_t)(bufi) * CTX_STAGE;                \
        const uint32_t bbs  = rawb + 24576u;                                    \
        _Pragma("unroll")                                                       \
        for (int c = 0; c < 4; c++) {                                           \
            cp_async16(rawb + ((uint32_t)rm_row * 32u + rm_sh + c * 4) * 4u,    \
                       A + (long long)(m0 + rm_row) * SS + (k0) + rm_sh + c * 4); \
        }                                                                       \
        _Pragma("unroll")                                                       \
        for (int c = 0; c < 2; c++) {                                           \
            cp_async16(bbs + SW_WORD(rm_row, (tid & 1) * 8 + c * 4) * 4u,       \
                       B + (long long)rm_row * SS + (k0) + (tid & 1) * 16 + c * 8); \
        }                                                                       \
    }

#define TRANSFORM(bufi, k0)                                                     \
    {                                                                           \
        const float* rawb = reinterpret_cast<const float*>(                     \
            smem + (uint32_t)(bufi) * CTX_STAGE);                               \
        char* pbase = smem + (uint32_t)(bufi) * CTX_STAGE + 16384u;             \
        const float rm = sM_s[rm_row], ri = sI_s[rm_row];                       \
        float pv[16];                                                           \
        _Pragma("unroll")                                                       \
        for (int j = 0; j < 16; j++)                                            \
            pv[j] = __expf(rawb[rm_row * 32 + rm_sh + j] - rm) * ri;            \
        _Pragma("unroll")                                                       \
        for (int c = 0; c < 4; c++)                                             \
            *reinterpret_cast<float4*>(AT + (long long)(m0 + rm_row) * SS + (k0) + rm_sh + c * 4) = \
                make_float4(pv[c*4], pv[c*4+1], pv[c*4+2], pv[c*4+3]);          \
        uint32_t wv[8];                                                         \
        _Pragma("unroll")                                                       \
        for (int j = 0; j < 8; j++) wv[j] = pack_h2(pv[2*j], pv[2*j+1]);        \
        *reinterpret_cast<uint4*>(pbase + SW_WORD(rm_row, (tid & 1) * 8) * 4u) = \
            make_uint4(wv[0], wv[1], wv[2], wv[3]);                             \
        *reinterpret_cast<uint4*>(pbase + SW_WORD(rm_row, (tid & 1) * 8 + 4) * 4u) = \
            make_uint4(wv[4], wv[5], wv[6], wv[7]);                             \
    }

    const int S = SS >> 5;   // 64 stages of 32 s-values

    // 3-stage ring: 2 stages in flight
    ISSUE_BODY(0, 0)   CP_COMMIT();
    ISSUE_BODY(1, 32)  CP_COMMIT();

    for (int s = 0; s < S; s++) {
        CP_WAIT1();
        __syncthreads();
        const int b = s % 3;
        TRANSFORM(b, s * 32)
        __syncthreads();
        {
            const uint32_t abuf = sb + (uint32_t)b * CTX_STAGE + 16384u;  // p region
            const uint32_t bbuf = sb + (uint32_t)b * CTX_STAGE + 24576u;  // vt region
            COMPUTE_FP16(abuf, bbuf)
        }
        if (s + 2 < S) {
            ISSUE_BODY((s + 2) % 3, (s + 2) * 32)
        }
        CP_COMMIT();
    }

    // ---- write ctx as fp16 (feeds out-projection) ----
#pragma unroll
    for (int nj = 0; nj < 4; nj++) {
        const int cc = warp_n * 32 + nj * 8 + tig * 2;
#pragma unroll
        for (int mi = 0; mi < 4; mi++) {
            const long long r0 = m0 + warp_m * 64 + mi * 16 + grp;
            const long long r1 = r0 + 8;
            uint32_t u0 = pack_h2(acc[mi][nj][0], acc[mi][nj][1]);
            uint32_t u1 = pack_h2(acc[mi][nj][2], acc[mi][nj][3]);
            *reinterpret_cast<uint32_t*>(C + r0 * DMODEL + cc) = u0;
            *reinterpret_cast<uint32_t*>(C + r1 * DMODEL + cc) = u1;
        }
    }
#undef ISSUE_BODY
#undef TRANSFORM
}

// ----------------------------------------------------------------------------
// V transpose (halves): g_v [(b*S+s)][h*128+n] -> g_vt [((b*8+h)*128+n)][s]
// ----------------------------------------------------------------------------
__global__ void transpose_v_kernel(const __half* __restrict__ v, __half* __restrict__ vt)
{
    __shared__ __half t[32][33];
    const int z = blockIdx.z, b = z >> 3, h = z & 7;
    const int s0 = blockIdx.x * 32, n0 = blockIdx.y * 32;
    const int tx = threadIdx.x, ty = threadIdx.y;
#pragma unroll
    for (int j = ty; j < 32; j += 8)
        t[j][tx] = v[((long long)b * SS + s0 + j) * DMODEL + h * DK + n0 + tx];
    __syncthreads();
#pragma unroll
    for (int j = ty; j < 32; j += 8)
        vt[((long long)z * DK + n0 + j) * SS + s0 + tx] = t[tx][j];
}

extern "C" void kernel_launch(void* const* d_in, const int* in_sizes, int n_in,
                              void* d_out, int out_size)
{
    const float* Q  = (const float*)d_in[0];
    const float* K  = (const float*)d_in[1];
    const float* V  = (const float*)d_in[2];
    const float* Wq = (const float*)d_in[3];
    const float* bq = (const float*)d_in[4];
    const float* Wk = (const float*)d_in[5];
    const float* bk = (const float*)d_in[6];
    const float* Wv = (const float*)d_in[7];
    const float* bv = (const float*)d_in[8];
    const float* Wo = (const float*)d_in[9];
    const float* bo = (const float*)d_in[10];

    float* out = (float*)d_out;

    const long long OUT_ELEMS  = (long long)BB * SS * DMODEL;
    const long long ATTN_ELEMS = (long long)NZ * SS * SS;

    __half *qp, *kp, *vp, *vtp, *ctxp, *wp, *inp;
    float *rawp, *sMp, *sSp, *rMp, *rIp;
    cudaGetSymbolAddress((void**)&qp,   g_q);
    cudaGetSymbolAddress((void**)&kp,   g_k);
    cudaGetSymbolAddress((void**)&vp,   g_v);
    cudaGetSymbolAddress((void**)&vtp,  g_vt);
    cudaGetSymbolAddress((void**)&ctxp, g_ctx);
    cudaGetSymbolAddress((void**)&rawp, g_raw);
    cudaGetSymbolAddress((void**)&sMp,  g_statsM);
    cudaGetSymbolAddress((void**)&sSp,  g_statsS);
    cudaGetSymbolAddress((void**)&rMp,  g_rowM);
    cudaGetSymbolAddress((void**)&rIp,  g_rowInv);
    cudaGetSymbolAddress((void**)&wp,   g_w);
    cudaGetSymbolAddress((void**)&inp,  g_in);

    float* attn = ((long long)out_size >= OUT_ELEMS + ATTN_ELEMS)
                      ? (out + OUT_ELEMS) : rawp;

    // <HAS_BIAS, STATS, OUT_HALF>
    auto projK  = gemm_fp16_kernel<true,  false, true >;
    auto scoreK = gemm_fp16_kernel<false, true,  false>;
    auto outK   = gemm_fp16_kernel<true,  false, false>;
    cudaFuncSetAttribute(projK,  cudaFuncAttributeMaxDynamicSharedMemorySize, GEMM_SMEM_BYTES);
    cudaFuncSetAttribute(scoreK, cudaFuncAttributeMaxDynamicSharedMemorySize, GEMM_SMEM_BYTES);
    cudaFuncSetAttribute(outK,   cudaFuncAttributeMaxDynamicSharedMemorySize, GEMM_SMEM_BYTES);
    cudaFuncSetAttribute(ctx_fused_kernel,
                         cudaFuncAttributeMaxDynamicSharedMemorySize, CTX_SMEM_BYTES);

    const int M = BB * SS;
    const float inv_sqrt_dk = 0.08838834764831845f;

    dim3 blk(256);

    // 0) prepass: convert weights + inputs to fp16
    {
        dim3 gW(DMODEL * DMODEL / (256 * 4), 1, 4);
        cvt_weights_kernel<<<gW, blk>>>(Wq, Wk, Wv, Wo, wp);
        dim3 gI((BB * SS * DMODEL) / (256 * 4), 1, 3);
        cvt_inputs_kernel<<<gI, blk>>>(Q, K, V, inp);
    }
    __half* wq = wp;
    __half* wk = wp + (size_t)DMODEL * DMODEL;
    __half* wv = wp + 2 * (size_t)DMODEL * DMODEL;
    __half* wo = wp + 3 * (size_t)DMODEL * DMODEL;
    __half* qin = inp;
    __half* kin = inp + (size_t)BB * SS * DMODEL;
    __half* vin = inp + 2 * (size_t)BB * SS * DMODEL;

    // 1-3) projections: X @ W^T + b -> fp16 q/k/v
    dim3 gProj(DMODEL / 128, M / 128, 1);
    projK<<<gProj, blk, GEMM_SMEM_BYTES>>>(qin, wq, bq, qp,
        DMODEL, DMODEL, DMODEL, DMODEL, 1.0f, 1, 0, 0, 0, 0, 0, 0, nullptr, nullptr);
    projK<<<gProj, blk, GEMM_SMEM_BYTES>>>(kin, wk, bk, kp,
        DMODEL, DMODEL, DMODEL, DMODEL, 1.0f, 1, 0, 0, 0, 0, 0, 0, nullptr, nullptr);
    projK<<<gProj, blk, GEMM_SMEM_BYTES>>>(vin, wv, bv, vp,
        DMODEL, DMODEL, DMODEL, DMODEL, 1.0f, 1, 0, 0, 0, 0, 0, 0, nullptr, nullptr);

    // 3b) transpose V per head (fp16)
    {
        dim3 gT(SS / 32, DK / 32, NZ);
        dim3 bT(32, 8);
        transpose_v_kernel<<<gT, bT>>>(vp, vtp);
    }

    // 4) raw scores (fp32) + per-tile softmax stats
    dim3 gScores(SS / 128, SS / 128, NZ);
    scoreK<<<gScores, blk, GEMM_SMEM_BYTES>>>(qp, kp, nullptr, rawp,
        DK, DMODEL, DMODEL, SS, inv_sqrt_dk,
        NHEADS,
        (long long)SS * DMODEL, (long long)DK,
        (long long)SS * DMODEL, (long long)DK,
        (long long)NHEADS * SS * SS, (long long)SS * SS,
        sMp, sSp);

    // 5) combine stats
    combine_stats_kernel<<<(NZ * SS) / 256, blk>>>(sMp, sSp, rMp, rIp);

    // 6) fused softmax + ctx GEMM (+ fp32 attn output write)
    {
        dim3 gCtx(1, SS / 128, NZ);
        ctx_fused_kernel<<<gCtx, blk, CTX_SMEM_BYTES>>>(rawp, vtp, ctxp, attn, rMp, rIp);
    }

    // 7) out = ctx @ Wo^T + bo (fp32 out)
    outK<<<gProj, blk, GEMM_SMEM_BYTES>>>(ctxp, wo, bo, out,
        DMODEL, DMODEL, DMODEL, DMODEL, 1.0f, 1, 0, 0, 0, 0, 0, 0, nullptr, nullptr);
}

// round 14
// speedup vs baseline: 1.4696x; 1.2088x over previous
#include <cuda_runtime.h>
#include <cuda_fp16.h>
#include <math.h>
#include <stdint.h>

#define DMODEL 1024
#define NHEADS 8
#define DK 128
#define BB 2
#define SS 2048
#define NZ (BB * NHEADS)          // 16
#define NTILE (SS / 128)          // 16

// Scratch (allocation-free rule: __device__ globals)
__device__ __half g_q[(size_t)BB * SS * DMODEL];
__device__ __half g_k[(size_t)BB * SS * DMODEL];
__device__ __half g_v[(size_t)BB * SS * DMODEL];
__device__ __half g_vt[(size_t)BB * NHEADS * DK * SS];
__device__ __half g_ctx[(size_t)BB * SS * DMODEL];
__device__ float  g_attn_fb[(size_t)NZ * SS * SS];      // attn fallback only
__device__ float  g_statsM[(size_t)NZ * SS * NTILE];
__device__ float  g_statsS[(size_t)NZ * SS * NTILE];
__device__ float  g_rowM[(size_t)NZ * SS];
__device__ float  g_rowInv[(size_t)NZ * SS];
__device__ __half g_w[4][(size_t)DMODEL * DMODEL];
__device__ __half g_in[3][(size_t)BB * SS * DMODEL];

__device__ __forceinline__ uint32_t smem_u32(const void* p) {
    uint32_t a;
    asm("{ .reg .u64 t; cvta.to.shared.u64 t, %1; cvt.u32.u64 %0, t; }" : "=r"(a) : "l"(p));
    return a;
}
__device__ __forceinline__ void mma_fp16(float* c, const uint32_t* a, const uint32_t* b) {
    asm volatile(
        "mma.sync.aligned.m16n8k16.row.col.f32.f16.f16.f32 "
        "{%0,%1,%2,%3},{%4,%5,%6,%7},{%8,%9},{%0,%1,%2,%3};"
        : "+f"(c[0]), "+f"(c[1]), "+f"(c[2]), "+f"(c[3])
        : "r"(a[0]), "r"(a[1]), "r"(a[2]), "r"(a[3]), "r"(b[0]), "r"(b[1]));
}
__device__ __forceinline__ void ldmatrix_x4(uint32_t* r, uint32_t addr) {
    asm volatile("ldmatrix.sync.aligned.m8n8.x4.shared.b16 {%0,%1,%2,%3}, [%4];"
                 : "=r"(r[0]), "=r"(r[1]), "=r"(r[2]), "=r"(r[3]) : "r"(addr));
}
__device__ __forceinline__ void cp_async16(uint32_t saddr, const void* gaddr) {
    asm volatile("cp.async.cg.shared.global [%0], [%1], 16;"
                 :: "r"(saddr), "l"(gaddr) : "memory");
}
#define CP_COMMIT() asm volatile("cp.async.commit_group;" ::: "memory")
#define CP_WAIT2()  asm volatile("cp.async.wait_group 2;" ::: "memory")
#define CP_WAIT1()  asm volatile("cp.async.wait_group 1;" ::: "memory")

__device__ __forceinline__ uint32_t pack_h2(float lo, float hi) {
    __half2 h = __floats2half2_rn(lo, hi);
    return *reinterpret_cast<uint32_t*>(&h);
}

// smem word index for (row m, k-word k) within a [128 x 32-half] sub-tile.
// Conflict-free for 16B cp.async stores, ldmatrix groups, and STS.32 fragments.
#define SW_WORD(m, k) ((uint32_t)(m) * 16u + ((uint32_t)(k) ^ (((((uint32_t)(m)) >> 1) & 3u) << 2)))

#define STAGE_BYTES 16384u        // A(8KB) + B(8KB) per 32-half k-stage
#define GEMM_SMEM_BYTES 65536u

// fused attention smem layout
#define FA_Q_OFF  0u              // 4 sub-tiles (dk)      32KB
#define FA_P_OFF  32768u          // 4 sub-tiles (s-local) 32KB
#define FA_KV_OFF 65536u          // stage b: k 32KB + vt 32KB
#define FA_KV_STAGE 65536u
#define FA_SMEM_BYTES (65536u + 2u * FA_KV_STAGE)   // 196608

// ldmatrix address prep (f16 m16n8k16), per [128x32-half] sub-tile
#define LDM_PREP()                                                              \
    uint32_t aBaseW[4], aXorW[4];                                               \
    _Pragma("unroll")                                                           \
    for (int mi = 0; mi < 4; mi++) {                                            \
        const int rowa = warp_m * 64 + mi * 16 + (lane & 7) + ((lane >> 3) & 1) * 8; \
        aBaseW[mi] = (uint32_t)rowa * 16u;                                      \
        aXorW[mi]  = (((uint32_t)rowa >> 1) & 3u) << 2;                         \
    }                                                                           \
    const uint32_t aKsel = ((uint32_t)lane >> 4) * 4u;                          \
    uint32_t bBaseW[2], bXorW[2];                                               \
    _Pragma("unroll")                                                           \
    for (int p = 0; p < 2; p++) {                                               \
        const int rowb = warp_n * 32 + p * 16 + (lane & 7) + ((lane >> 4) & 1) * 8; \
        bBaseW[p] = (uint32_t)rowb * 16u;                                       \
        bXorW[p]  = (((uint32_t)rowb >> 1) & 3u) << 2;                          \
    }                                                                           \
    const uint32_t bKsel = (((uint32_t)lane >> 3) & 1u) * 4u;

// 2 x k16 mma steps over one 32-half sub-tile pair, into named accumulator.
#define COMPUTE_FP16(accN, abufAddr, bbufAddr)                                  \
    {                                                                           \
        _Pragma("unroll")                                                       \
        for (int ks = 0; ks < 2; ks++) {                                        \
            const uint32_t kb = ks * 8;                                         \
            uint32_t af[4][4], bf[2][4];                                        \
            _Pragma("unroll")                                                   \
            for (int mi = 0; mi < 4; mi++) {                                    \
                const uint32_t kw = kb + aKsel;                                 \
                ldmatrix_x4(af[mi], (abufAddr) + (aBaseW[mi] + (kw ^ aXorW[mi])) * 4u); \
            }                                                                   \
            _Pragma("unroll")                                                   \
            for (int p = 0; p < 2; p++) {                                       \
                const uint32_t kw = kb + bKsel;                                 \
                ldmatrix_x4(bf[p], (bbufAddr) + (bBaseW[p] + (kw ^ bXorW[p])) * 4u); \
            }                                                                   \
            _Pragma("unroll")                                                   \
            for (int mi = 0; mi < 4; mi++)                                      \
                _Pragma("unroll")                                               \
                for (int nj = 0; nj < 4; nj++)                                  \
                    mma_fp16(accN[mi][nj], af[mi], &bf[nj >> 1][(nj & 1) * 2]); \
        }                                                                       \
    }

// ============================================================================
// Batched FP16 GEMM (cp.async 4-stage):  C = alpha * A @ B^T + bias
//   WRITE_C=false: stats-only (scores pass, no C write).
// ============================================================================
template <bool HAS_BIAS, bool STATS, bool OUT_HALF, bool WRITE_C>
__global__ __launch_bounds__(256, 2) void gemm_fp16_kernel(
    const __half* __restrict__ A, const __half* __restrict__ B,
    const float* __restrict__ bias, void* __restrict__ Cv,
    int K, int lda, int ldb, int ldc, float alpha,
    int Hdiv,
    long long sAb, long long sAh,
    long long sBb, long long sBh,
    long long sCb, long long sCh,
    float* __restrict__ statsM, float* __restrict__ statsS)
{
    extern __shared__ char smem[];
    const uint32_t sb = smem_u32(smem);

    const int z  = blockIdx.z;
    const int zb = z / Hdiv;
    const int zh = z % Hdiv;
    A += zb * sAb + zh * sAh;
    B += zb * sBb + zh * sBh;
    const long long coff = zb * sCb + zh * sCh;

    const int tid  = threadIdx.x;
    const int wid  = tid >> 5;
    const int lane = tid & 31;
    const int m0   = blockIdx.y * 128;
    const int n0   = blockIdx.x * 128;
    const int warp_m = wid >> 2;
    const int warp_n = wid & 3;
    const int grp  = lane >> 2;
    const int tig  = lane & 3;

    const int lm  = tid >> 2;
    const int lcw = (tid & 3) * 4;
    const int lch = (tid & 3) * 8;

    LDM_PREP()

    float acc[4][4][4];
#pragma unroll
    for (int i = 0; i < 4; i++)
#pragma unroll
        for (int j = 0; j < 4; j++)
#pragma unroll
            for (int q = 0; q < 4; q++) acc[i][j][q] = 0.0f;

#define ISSUE_BODY(bufi, k0)                                                    \
    {                                                                           \
        const uint32_t ab = sb + (uint32_t)(bufi) * STAGE_BYTES;                \
        const uint32_t bbs = ab + 8192u;                                        \
        _Pragma("unroll")                                                       \
        for (int i = 0; i < 2; i++) {                                           \
            const int m = lm + i * 64;                                          \
            cp_async16(ab + SW_WORD(m, lcw) * 4u,                               \
                       A + (long long)(m0 + m) * lda + (k0) + lch);             \
            cp_async16(bbs + SW_WORD(m, lcw) * 4u,                              \
                       B + (long long)(n0 + m) * ldb + (k0) + lch);             \
        }                                                                       \
    }

    const int S = K >> 5;

    ISSUE_BODY(0, 0)   CP_COMMIT();
    ISSUE_BODY(1, 32)  CP_COMMIT();
    ISSUE_BODY(2, 64)  CP_COMMIT();

    for (int s = 0; s < S; s++) {
        CP_WAIT2();
        __syncthreads();
        {
            const uint32_t abuf = sb + (uint32_t)(s & 3) * STAGE_BYTES;
            const uint32_t bbuf = abuf + 8192u;
            COMPUTE_FP16(acc, abuf, bbuf)
        }
        if (s + 3 < S) {
            ISSUE_BODY((s + 3) & 3, (s + 3) * 32)
        }
        CP_COMMIT();
    }

    // ---- write C ----
    if (WRITE_C) {
#pragma unroll
        for (int nj = 0; nj < 4; nj++) {
            const int cc = n0 + warp_n * 32 + nj * 8 + tig * 2;
            float b0 = 0.0f, b1 = 0.0f;
            if (HAS_BIAS) { b0 = bias[cc]; b1 = bias[cc + 1]; }
#pragma unroll
            for (int mi = 0; mi < 4; mi++) {
                const long long r0 = m0 + warp_m * 64 + mi * 16 + grp;
                const long long r1 = r0 + 8;
                const float x0 = alpha * acc[mi][nj][0] + b0;
                const float x1 = alpha * acc[mi][nj][1] + b1;
                const float x2 = alpha * acc[mi][nj][2] + b0;
                const float x3 = alpha * acc[mi][nj][3] + b1;
                if (OUT_HALF) {
                    __half* C = reinterpret_cast<__half*>(Cv) + coff;
                    *reinterpret_cast<uint32_t*>(C + r0 * ldc + cc) = pack_h2(x0, x1);
                    *reinterpret_cast<uint32_t*>(C + r1 * ldc + cc) = pack_h2(x2, x3);
                } else {
                    float* C = reinterpret_cast<float*>(Cv) + coff;
                    *reinterpret_cast<float2*>(C + r0 * ldc + cc) = make_float2(x0, x1);
                    *reinterpret_cast<float2*>(C + r1 * ldc + cc) = make_float2(x2, x3);
                }
            }
        }
    }

    // ---- per-tile softmax stats (scores pass) ----
    if (STATS) {
        __syncthreads();
        float* sred    = reinterpret_cast<float*>(smem);
        float* rowmaxs = reinterpret_cast<float*>(smem) + 512;

#pragma unroll
        for (int mi = 0; mi < 4; mi++) {
#pragma unroll
            for (int h = 0; h < 2; h++) {
                float mx = -1e30f;
#pragma unroll
                for (int nj = 0; nj < 4; nj++)
                    mx = fmaxf(mx, fmaxf(alpha * acc[mi][nj][h * 2],
                                         alpha * acc[mi][nj][h * 2 + 1]));
                mx = fmaxf(mx, __shfl_xor_sync(0xffffffffu, mx, 1));
                mx = fmaxf(mx, __shfl_xor_sync(0xffffffffu, mx, 2));
                const int rl = warp_m * 64 + mi * 16 + grp + h * 8;
                if (tig == 0) sred[warp_n * 128 + rl] = mx;
            }
        }
        __syncthreads();
        if (tid < 128) {
            float rm = fmaxf(fmaxf(sred[tid], sred[128 + tid]),
                             fmaxf(sred[256 + tid], sred[384 + tid]));
            rowmaxs[tid] = rm;
        }
        __syncthreads();

#pragma unroll
        for (int mi = 0; mi < 4; mi++) {
#pragma unroll
            for (int h = 0; h < 2; h++) {
                const int rl = warp_m * 64 + mi * 16 + grp + h * 8;
                const float rm = rowmaxs[rl];
                float s = 0.0f;
#pragma unroll
                for (int nj = 0; nj < 4; nj++) {
                    s += __expf(alpha * acc[mi][nj][h * 2]     - rm);
                    s += __expf(alpha * acc[mi][nj][h * 2 + 1] - rm);
                }
                s += __shfl_xor_sync(0xffffffffu, s, 1);
                s += __shfl_xor_sync(0xffffffffu, s, 2);
                if (tig == 0) sred[warp_n * 128 + rl] = s;
            }
        }
        __syncthreads();
        if (tid < 128) {
            const float sg = sred[tid] + sred[128 + tid] + sred[256 + tid] + sred[384 + tid];
            const long long gi = ((long long)z * SS + m0 + tid) * NTILE + blockIdx.x;
            statsM[gi] = rowmaxs[tid];
            statsS[gi] = sg;
        }
    }
#undef ISSUE_BODY
}

// ============================================================================
// Fused flash attention pass: recompute scores, softmax, write attn, p @ vt.
//   grid: (1, 16 m-blocks, 16 z).  q persistent; k/vt double-buffered.
//   NOTE: __syncthreads() after ctx mma, BEFORE ISSUE_KV — the issue targets
//   the buffer just read; without the barrier fast warps overwrite data slow
//   warps are still reading (the R13 race).
// ============================================================================
__global__ __launch_bounds__(256, 1) void attn_flash_kernel(
    const __half* __restrict__ Qp, const __half* __restrict__ Kp,
    const __half* __restrict__ VTp, __half* __restrict__ CTX,
    float* __restrict__ ATTN,
    const float* __restrict__ rowM, const float* __restrict__ rowInv,
    float alpha)
{
    extern __shared__ char smem[];
    const uint32_t sb = smem_u32(smem);

    const int z  = blockIdx.z;
    const int zb = z >> 3;
    const int zh = z & 7;
    const int m0 = blockIdx.y * 128;

    const __half* Qg = Qp + ((long long)zb * SS + m0) * DMODEL + zh * DK;
    const __half* Kg = Kp + (long long)zb * SS * DMODEL + zh * DK;
    const __half* Vg = VTp + (long long)z * DK * SS;
    __half* Cg = CTX + ((long long)zb * SS + m0) * DMODEL + zh * DK;
    float* Ag = ATTN + ((long long)z * SS + m0) * SS;

    const int tid  = threadIdx.x;
    const int wid  = tid >> 5;
    const int lane = tid & 31;
    const int warp_m = wid >> 2;
    const int warp_n = wid & 3;
    const int grp  = lane >> 2;
    const int tig  = lane & 3;

    const int lm  = tid >> 2;
    const int lcw = (tid & 3) * 4;
    const int lch = (tid & 3) * 8;

    LDM_PREP()

    // per-thread row stats (8 rows each thread touches)
    float mlo[4], mhi[4], ilo[4], ihi[4];
#pragma unroll
    for (int mi = 0; mi < 4; mi++) {
        const long long r = (long long)z * SS + m0 + warp_m * 64 + mi * 16 + grp;
        mlo[mi] = rowM[r];     ilo[mi] = rowInv[r];
        mhi[mi] = rowM[r + 8]; ihi[mi] = rowInv[r + 8];
    }

    float cacc[4][4][4];
#pragma unroll
    for (int i = 0; i < 4; i++)
#pragma unroll
        for (int j = 0; j < 4; j++)
#pragma unroll
            for (int q = 0; q < 4; q++) cacc[i][j][q] = 0.0f;

    // ---- load q block (4 dk sub-tiles) ----
#pragma unroll
    for (int t = 0; t < 4; t++)
#pragma unroll
        for (int i = 0; i < 2; i++) {
            const int m = lm + i * 64;
            cp_async16(sb + FA_Q_OFF + t * 8192u + SW_WORD(m, lcw) * 4u,
                       Qg + (long long)m * DMODEL + t * 32 + lch);
        }

#define ISSUE_KV(bufi, s0)                                                      \
    {                                                                           \
        const uint32_t kb_ = sb + FA_KV_OFF + (uint32_t)(bufi) * FA_KV_STAGE;   \
        const uint32_t vb_ = kb_ + 32768u;                                      \
        _Pragma("unroll")                                                       \
        for (int t = 0; t < 4; t++)                                             \
            _Pragma("unroll")                                                   \
            for (int i = 0; i < 2; i++) {                                       \
                const int m = lm + i * 64;                                      \
                cp_async16(kb_ + t * 8192u + SW_WORD(m, lcw) * 4u,              \
                           Kg + (long long)((s0) + m) * DMODEL + t * 32 + lch); \
                cp_async16(vb_ + t * 8192u + SW_WORD(m, lcw) * 4u,              \
                           Vg + (long long)m * SS + (s0) + t * 32 + lch);       \
            }                                                                   \
    }

    // prologue: q + chunk0 in group0, chunk1 in group1
    ISSUE_KV(0, 0)    CP_COMMIT();
    ISSUE_KV(1, 128)  CP_COMMIT();

    for (int ch = 0; ch < NTILE; ch++) {
        const int s0 = ch * 128;
        const int b  = ch & 1;
        const uint32_t kbuf = sb + FA_KV_OFF + (uint32_t)b * FA_KV_STAGE;
        const uint32_t vbuf = kbuf + 32768u;

        CP_WAIT1();
        __syncthreads();

        // ---- scores tile: q @ k^T, K = dk = 4 sub-tiles ----
        float sacc[4][4][4];
#pragma unroll
        for (int i = 0; i < 4; i++)
#pragma unroll
            for (int j = 0; j < 4; j++)
#pragma unroll
                for (int q = 0; q < 4; q++) sacc[i][j][q] = 0.0f;
#pragma unroll
        for (int t = 0; t < 4; t++) {
            const uint32_t qa = sb + FA_Q_OFF + t * 8192u;
            const uint32_t ka = kbuf + t * 8192u;
            COMPUTE_FP16(sacc, qa, ka)
        }

        // ---- transform: p = exp(alpha*s - M) * inv ; write attn + p smem ----
#pragma unroll
        for (int mi = 0; mi < 4; mi++) {
#pragma unroll
            for (int nj = 0; nj < 4; nj++) {
                const int cc = warp_n * 32 + nj * 8 + tig * 2;
                const float p00 = __expf(alpha * sacc[mi][nj][0] - mlo[mi]) * ilo[mi];
                const float p01 = __expf(alpha * sacc[mi][nj][1] - mlo[mi]) * ilo[mi];
                const float p10 = __expf(alpha * sacc[mi][nj][2] - mhi[mi]) * ihi[mi];
                const float p11 = __expf(alpha * sacc[mi][nj][3] - mhi[mi]) * ihi[mi];
                const int rlo = warp_m * 64 + mi * 16 + grp;
                *reinterpret_cast<float2*>(Ag + (long long)rlo * SS + s0 + cc) =
                    make_float2(p00, p01);
                *reinterpret_cast<float2*>(Ag + (long long)(rlo + 8) * SS + s0 + cc) =
                    make_float2(p10, p11);
                const uint32_t pw = (uint32_t)(nj * 4 + tig);
                const uint32_t poff = FA_P_OFF + (uint32_t)warp_n * 8192u;
                *reinterpret_cast<uint32_t*>(smem + poff + SW_WORD(rlo, pw) * 4u) =
                    pack_h2(p00, p01);
                *reinterpret_cast<uint32_t*>(smem + poff + SW_WORD(rlo + 8, pw) * 4u) =
                    pack_h2(p10, p11);
            }
        }
        __syncthreads();

        // ---- ctx mma: p @ vt^T, K = s-chunk = 4 sub-tiles ----
#pragma unroll
        for (int t = 0; t < 4; t++) {
            const uint32_t pa = sb + FA_P_OFF + t * 8192u;
            const uint32_t va = vbuf + t * 8192u;
            COMPUTE_FP16(cacc, pa, va)
        }

        // RACE FIX: all warps must finish reading kbuf/vbuf (buffer b) before
        // any warp issues cp.async writes into the SAME buffer for chunk ch+2.
        __syncthreads();

        if (ch + 2 < NTILE) {
            ISSUE_KV(b, (ch + 2) * 128)
        }
        CP_COMMIT();   // unconditional: exact tail accounting
    }

    // ---- write ctx fp16 ----
#pragma unroll
    for (int nj = 0; nj < 4; nj++) {
        const int cc = warp_n * 32 + nj * 8 + tig * 2;
#pragma unroll
        for (int mi = 0; mi < 4; mi++) {
            const long long r0 = warp_m * 64 + mi * 16 + grp;
            const long long r1 = r0 + 8;
            *reinterpret_cast<uint32_t*>(Cg + r0 * DMODEL + cc) =
                pack_h2(cacc[mi][nj][0], cacc[mi][nj][1]);
            *reinterpret_cast<uint32_t*>(Cg + r1 * DMODEL + cc) =
                pack_h2(cacc[mi][nj][2], cacc[mi][nj][3]);
        }
    }
#undef ISSUE_KV
}

// ============================================================================
// Prepass converters + stats combine + V transpose
// ============================================================================
__global__ __launch_bounds__(256) void cvt_weights_kernel(
    const float* __restrict__ w0, const float* __restrict__ w1,
    const float* __restrict__ w2, const float* __restrict__ w3,
    __half* __restrict__ dst)
{
    const float* src = (blockIdx.z == 0) ? w0 : (blockIdx.z == 1) ? w1
                     : (blockIdx.z == 2) ? w2 : w3;
    __half* d = dst + (size_t)blockIdx.z * DMODEL * DMODEL;
    const long long i = ((long long)blockIdx.x * 256 + threadIdx.x) * 4;
    float4 v = *reinterpret_cast<const float4*>(src + i);
    uint2 u;
    u.x = pack_h2(v.x, v.y);
    u.y = pack_h2(v.z, v.w);
    *reinterpret_cast<uint2*>(d + i) = u;
}

__global__ __launch_bounds__(256) void cvt_inputs_kernel(
    const float* __restrict__ x0, const float* __restrict__ x1,
    const float* __restrict__ x2, __half* __restrict__ dst)
{
    const float* src = (blockIdx.z == 0) ? x0 : (blockIdx.z == 1) ? x1 : x2;
    __half* d = dst + (size_t)blockIdx.z * BB * SS * DMODEL;
    const long long i = ((long long)blockIdx.x * 256 + threadIdx.x) * 4;
    float4 v = *reinterpret_cast<const float4*>(src + i);
    uint2 u;
    u.x = pack_h2(v.x, v.y);
    u.y = pack_h2(v.z, v.w);
    *reinterpret_cast<uint2*>(d + i) = u;
}

__global__ __launch_bounds__(256) void combine_stats_kernel(
    const float* __restrict__ sM, const float* __restrict__ sS,
    float* __restrict__ rowM, float* __restrict__ rowInv)
{
    const long long r = (long long)blockIdx.x * 256 + threadIdx.x;
    const float* pm = sM + r * NTILE;
    const float* ps = sS + r * NTILE;
    float M = -1e30f;
#pragma unroll
    for (int t = 0; t < NTILE; t++) M = fmaxf(M, pm[t]);
    float S = 0.0f;
#pragma unroll
    for (int t = 0; t < NTILE; t++) S += ps[t] * __expf(pm[t] - M);
    rowM[r]   = M;
    rowInv[r] = 1.0f / S;
}

__global__ void transpose_v_kernel(const __half* __restrict__ v, __half* __restrict__ vt)
{
    __shared__ __half t[32][33];
    const int z = blockIdx.z, b = z >> 3, h = z & 7;
    const int s0 = blockIdx.x * 32, n0 = blockIdx.y * 32;
    const int tx = threadIdx.x, ty = threadIdx.y;
#pragma unroll
    for (int j = ty; j < 32; j += 8)
        t[j][tx] = v[((long long)b * SS + s0 + j) * DMODEL + h * DK + n0 + tx];
    __syncthreads();
#pragma unroll
    for (int j = ty; j < 32; j += 8)
        vt[((long long)z * DK + n0 + j) * SS + s0 + tx] = t[tx][j];
}

extern "C" void kernel_launch(void* const* d_in, const int* in_sizes, int n_in,
                              void* d_out, int out_size)
{
    const float* Q  = (const float*)d_in[0];
    const float* K  = (const float*)d_in[1];
    const float* V  = (const float*)d_in[2];
    const float* Wq = (const float*)d_in[3];
    const float* bq = (const float*)d_in[4];
    const float* Wk = (const float*)d_in[5];
    const float* bk = (const float*)d_in[6];
    const float* Wv = (const float*)d_in[7];
    const float* bv = (const float*)d_in[8];
    const float* Wo = (const float*)d_in[9];
    const float* bo = (const float*)d_in[10];

    float* out = (float*)d_out;

    const long long OUT_ELEMS  = (long long)BB * SS * DMODEL;
    const long long ATTN_ELEMS = (long long)NZ * SS * SS;

    __half *qp, *kp, *vp, *vtp, *ctxp, *wp, *inp;
    float *fbp, *sMp, *sSp, *rMp, *rIp;
    cudaGetSymbolAddress((void**)&qp,   g_q);
    cudaGetSymbolAddress((void**)&kp,   g_k);
    cudaGetSymbolAddress((void**)&vp,   g_v);
    cudaGetSymbolAddress((void**)&vtp,  g_vt);
    cudaGetSymbolAddress((void**)&ctxp, g_ctx);
    cudaGetSymbolAddress((void**)&fbp,  g_attn_fb);
    cudaGetSymbolAddress((void**)&sMp,  g_statsM);
    cudaGetSymbolAddress((void**)&sSp,  g_statsS);
    cudaGetSymbolAddress((void**)&rMp,  g_rowM);
    cudaGetSymbolAddress((void**)&rIp,  g_rowInv);
    cudaGetSymbolAddress((void**)&wp,   g_w);
    cudaGetSymbolAddress((void**)&inp,  g_in);

    float* attn = ((long long)out_size >= OUT_ELEMS + ATTN_ELEMS)
                      ? (out + OUT_ELEMS) : fbp;

    // <HAS_BIAS, STATS, OUT_HALF, WRITE_C>
    auto projK  = gemm_fp16_kernel<true,  false, true,  true >;
    auto statsK = gemm_fp16_kernel<false, true,  false, false>;
    auto outK   = gemm_fp16_kernel<true,  false, false, true >;
    cudaFuncSetAttribute(projK,  cudaFuncAttributeMaxDynamicSharedMemorySize, GEMM_SMEM_BYTES);
    cudaFuncSetAttribute(statsK, cudaFuncAttributeMaxDynamicSharedMemorySize, GEMM_SMEM_BYTES);
    cudaFuncSetAttribute(outK,   cudaFuncAttributeMaxDynamicSharedMemorySize, GEMM_SMEM_BYTES);
    cudaFuncSetAttribute(attn_flash_kernel,
                         cudaFuncAttributeMaxDynamicSharedMemorySize, FA_SMEM_BYTES);

    const int M = BB * SS;
    const float inv_sqrt_dk = 0.08838834764831845f;

    dim3 blk(256);

    // 0) prepass: convert weights + inputs to fp16
    {
        dim3 gW(DMODEL * DMODEL / (256 * 4), 1, 4);
        cvt_weights_kernel<<<gW, blk>>>(Wq, Wk, Wv, Wo, wp);
        dim3 gI((BB * SS * DMODEL) / (256 * 4), 1, 3);
        cvt_inputs_kernel<<<gI, blk>>>(Q, K, V, inp);
    }
    __half* wq = wp;
    __half* wk = wp + (size_t)DMODEL * DMODEL;
    __half* wv = wp + 2 * (size_t)DMODEL * DMODEL;
    __half* wo = wp + 3 * (size_t)DMODEL * DMODEL;
    __half* qin = inp;
    __half* kin = inp + (size_t)BB * SS * DMODEL;
    __half* vin = inp + 2 * (size_t)BB * SS * DMODEL;

    // 1-3) projections
    dim3 gProj(DMODEL / 128, M / 128, 1);
    projK<<<gProj, blk, GEMM_SMEM_BYTES>>>(qin, wq, bq, qp,
        DMODEL, DMODEL, DMODEL, DMODEL, 1.0f, 1, 0, 0, 0, 0, 0, 0, nullptr, nullptr);
    projK<<<gProj, blk, GEMM_SMEM_BYTES>>>(kin, wk, bk, kp,
        DMODEL, DMODEL, DMODEL, DMODEL, 1.0f, 1, 0, 0, 0, 0, 0, 0, nullptr, nullptr);
    projK<<<gProj, blk, GEMM_SMEM_BYTES>>>(vin, wv, bv, vp,
        DMODEL, DMODEL, DMODEL, DMODEL, 1.0f, 1, 0, 0, 0, 0, 0, 0, nullptr, nullptr);

    // 3b) transpose V per head
    {
        dim3 gT(SS / 32, DK / 32, NZ);
        dim3 bT(32, 8);
        transpose_v_kernel<<<gT, bT>>>(vp, vtp);
    }

    // 4) stats pass: q @ k^T tile stats only (no score write)
    dim3 gScores(SS / 128, SS / 128, NZ);
    statsK<<<gScores, blk, GEMM_SMEM_BYTES>>>(qp, kp, nullptr, nullptr,
        DK, DMODEL, DMODEL, SS, inv_sqrt_dk,
        NHEADS,
        (long long)SS * DMODEL, (long long)DK,
        (long long)SS * DMODEL, (long long)DK,
        0, 0,
        sMp, sSp);

    // 5) combine stats
    combine_stats_kernel<<<(NZ * SS) / 256, blk>>>(sMp, sSp, rMp, rIp);

    // 6) fused flash pass: recompute scores, softmax, attn write, p @ vt
    {
        dim3 gF(1, SS / 128, NZ);
        attn_flash_kernel<<<gF, blk, FA_SMEM_BYTES>>>(qp, kp, vtp, ctxp, attn,
                                                      rMp, rIp, inv_sqrt_dk);
    }

    // 7) out = ctx @ Wo^T + bo
    outK<<<gProj, blk, GEMM_SMEM_BYTES>>>(ctxp, wo, bo, out,
        DMODEL, DMODEL, DMODEL, DMODEL, 1.0f, 1, 0, 0, 0, 0, 0, 0, nullptr, nullptr);
}

// round 15
// speedup vs baseline: 1.4861x; 1.0113x over previous
#include <cuda_runtime.h>
#include <cuda_fp16.h>
#include <math.h>
#include <stdint.h>

#define DMODEL 1024
#define NHEADS 8
#define DK 128
#define BB 2
#define SS 2048
#define NZ (BB * NHEADS)          // 16
#define NTILE (SS / 128)          // 16

// Scratch (allocation-free rule: __device__ globals)
__device__ __half g_q[(size_t)BB * SS * DMODEL];
__device__ __half g_k[(size_t)BB * SS * DMODEL];
__device__ __half g_v[(size_t)BB * SS * DMODEL];
__device__ __half g_vt[(size_t)BB * NHEADS * DK * SS];
__device__ __half g_ctx[(size_t)BB * SS * DMODEL];
__device__ float  g_attn_fb[(size_t)NZ * SS * SS];      // attn fallback only
__device__ float  g_statsM[(size_t)NZ * SS * NTILE];
__device__ float  g_statsS[(size_t)NZ * SS * NTILE];
__device__ float  g_rowM[(size_t)NZ * SS];
__device__ float  g_rowInv[(size_t)NZ * SS];
__device__ __half g_w[4][(size_t)DMODEL * DMODEL];
__device__ __half g_in[3][(size_t)BB * SS * DMODEL];

__device__ __forceinline__ uint32_t smem_u32(const void* p) {
    uint32_t a;
    asm("{ .reg .u64 t; cvta.to.shared.u64 t, %1; cvt.u32.u64 %0, t; }" : "=r"(a) : "l"(p));
    return a;
}
__device__ __forceinline__ void mma_fp16(float* c, const uint32_t* a, const uint32_t* b) {
    asm volatile(
        "mma.sync.aligned.m16n8k16.row.col.f32.f16.f16.f32 "
        "{%0,%1,%2,%3},{%4,%5,%6,%7},{%8,%9},{%0,%1,%2,%3};"
        : "+f"(c[0]), "+f"(c[1]), "+f"(c[2]), "+f"(c[3])
        : "r"(a[0]), "r"(a[1]), "r"(a[2]), "r"(a[3]), "r"(b[0]), "r"(b[1]));
}
__device__ __forceinline__ void ldmatrix_x4(uint32_t* r, uint32_t addr) {
    asm volatile("ldmatrix.sync.aligned.m8n8.x4.shared.b16 {%0,%1,%2,%3}, [%4];"
                 : "=r"(r[0]), "=r"(r[1]), "=r"(r[2]), "=r"(r[3]) : "r"(addr));
}
__device__ __forceinline__ void cp_async16(uint32_t saddr, const void* gaddr) {
    asm volatile("cp.async.cg.shared.global [%0], [%1], 16;"
                 :: "r"(saddr), "l"(gaddr) : "memory");
}
#define CP_COMMIT() asm volatile("cp.async.commit_group;" ::: "memory")
#define CP_WAIT1()  asm volatile("cp.async.wait_group 1;" ::: "memory")

__device__ __forceinline__ uint32_t pack_h2(float lo, float hi) {
    __half2 h = __floats2half2_rn(lo, hi);
    return *reinterpret_cast<uint32_t*>(&h);
}
__device__ __forceinline__ void stcs_f2(float* p, float x, float y) {
    asm volatile("st.global.cs.v2.f32 [%0], {%1, %2};" :: "l"(p), "f"(x), "f"(y) : "memory");
}

// smem word index for (row m, k-word k) within a [128 x 32-half] sub-tile.
// Conflict-free for 16B cp.async stores, ldmatrix groups, and STS.32 fragments.
#define SW_WORD(m, k) ((uint32_t)(m) * 16u + ((uint32_t)(k) ^ (((((uint32_t)(m)) >> 1) & 3u) << 2)))

#define STAGE_BYTES 16384u        // A(8KB) + B(8KB) per 32-half stage
#define GEMM_SMEM_BYTES 98304u    // 6 stages = 3 pair-groups

// fused attention smem layout
#define FA_Q_OFF  0u              // 4 sub-tiles (dk)      32KB
#define FA_P_OFF  32768u          // 4 sub-tiles (s-local) 32KB
#define FA_KV_OFF 65536u          // stage b: k 32KB + vt 32KB
#define FA_KV_STAGE 65536u
#define FA_SMEM_BYTES (65536u + 2u * FA_KV_STAGE)   // 196608

// ldmatrix address prep (f16 m16n8k16), per [128x32-half] sub-tile
#define LDM_PREP()                                                              \
    uint32_t aBaseW[4], aXorW[4];                                               \
    _Pragma("unroll")                                                           \
    for (int mi = 0; mi < 4; mi++) {                                            \
        const int rowa = warp_m * 64 + mi * 16 + (lane & 7) + ((lane >> 3) & 1) * 8; \
        aBaseW[mi] = (uint32_t)rowa * 16u;                                      \
        aXorW[mi]  = (((uint32_t)rowa >> 1) & 3u) << 2;                         \
    }                                                                           \
    const uint32_t aKsel = ((uint32_t)lane >> 4) * 4u;                          \
    uint32_t bBaseW[2], bXorW[2];                                               \
    _Pragma("unroll")                                                           \
    for (int p = 0; p < 2; p++) {                                               \
        const int rowb = warp_n * 32 + p * 16 + (lane & 7) + ((lane >> 4) & 1) * 8; \
        bBaseW[p] = (uint32_t)rowb * 16u;                                       \
        bXorW[p]  = (((uint32_t)rowb >> 1) & 3u) << 2;                          \
    }                                                                           \
    const uint32_t bKsel = (((uint32_t)lane >> 3) & 1u) * 4u;

// 2 x k16 mma steps over one 32-half sub-tile pair, into named accumulator.
#define COMPUTE_FP16(accN, abufAddr, bbufAddr)                                  \
    {                                                                           \
        _Pragma("unroll")                                                       \
        for (int ks = 0; ks < 2; ks++) {                                        \
            const uint32_t kb = ks * 8;                                         \
            uint32_t af[4][4], bf[2][4];                                        \
            _Pragma("unroll")                                                   \
            for (int mi = 0; mi < 4; mi++) {                                    \
                const uint32_t kw = kb + aKsel;                                 \
                ldmatrix_x4(af[mi], (abufAddr) + (aBaseW[mi] + (kw ^ aXorW[mi])) * 4u); \
            }                                                                   \
            _Pragma("unroll")                                                   \
            for (int p = 0; p < 2; p++) {                                       \
                const uint32_t kw = kb + bKsel;                                 \
                ldmatrix_x4(bf[p], (bbufAddr) + (bBaseW[p] + (kw ^ bXorW[p])) * 4u); \
            }                                                                   \
            _Pragma("unroll")                                                   \
            for (int mi = 0; mi < 4; mi++)                                      \
                _Pragma("unroll")                                               \
                for (int nj = 0; nj < 4; nj++)                                  \
                    mma_fp16(accN[mi][nj], af[mi], &bf[nj >> 1][(nj & 1) * 2]); \
        }                                                                       \
    }

// ============================================================================
// Batched FP16 GEMM, pair-grouped cp.async pipeline (1 barrier / 64 halves).
//   C = alpha * A @ B^T + bias.  WRITE_C=false: stats-only.
//   K % 64 == 0, K >= 128.
// ============================================================================
template <bool HAS_BIAS, bool STATS, bool OUT_HALF, bool WRITE_C>
__global__ __launch_bounds__(256, 2) void gemm_fp16_kernel(
    const __half* __restrict__ A, const __half* __restrict__ B,
    const float* __restrict__ bias, void* __restrict__ Cv,
    int K, int lda, int ldb, int ldc, float alpha,
    int Hdiv,
    long long sAb, long long sAh,
    long long sBb, long long sBh,
    long long sCb, long long sCh,
    float* __restrict__ statsM, float* __restrict__ statsS)
{
    extern __shared__ char smem[];
    const uint32_t sb = smem_u32(smem);

    const int z  = blockIdx.z;
    const int zb = z / Hdiv;
    const int zh = z % Hdiv;
    A += zb * sAb + zh * sAh;
    B += zb * sBb + zh * sBh;
    const long long coff = zb * sCb + zh * sCh;

    const int tid  = threadIdx.x;
    const int wid  = tid >> 5;
    const int lane = tid & 31;
    const int m0   = blockIdx.y * 128;
    const int n0   = blockIdx.x * 128;
    const int warp_m = wid >> 2;
    const int warp_n = wid & 3;
    const int grp  = lane >> 2;
    const int tig  = lane & 3;

    const int lm  = tid >> 2;
    const int lcw = (tid & 3) * 4;
    const int lch = (tid & 3) * 8;

    LDM_PREP()

    float acc[4][4][4];
#pragma unroll
    for (int i = 0; i < 4; i++)
#pragma unroll
        for (int j = 0; j < 4; j++)
#pragma unroll
            for (int q = 0; q < 4; q++) acc[i][j][q] = 0.0f;

#define ISSUE_BODY(bufi, k0)                                                    \
    {                                                                           \
        const uint32_t ab = sb + (uint32_t)(bufi) * STAGE_BYTES;                \
        const uint32_t bbs = ab + 8192u;                                        \
        _Pragma("unroll")                                                       \
        for (int i = 0; i < 2; i++) {                                           \
            const int m = lm + i * 64;                                          \
            cp_async16(ab + SW_WORD(m, lcw) * 4u,                               \
                       A + (long long)(m0 + m) * lda + (k0) + lch);             \
            cp_async16(bbs + SW_WORD(m, lcw) * 4u,                              \
                       B + (long long)(n0 + m) * ldb + (k0) + lch);             \
        }                                                                       \
    }

    const int G = K >> 6;   // pair-groups of 64 halves (2 stages each)

    // prologue: 2 pair-groups in flight (pairs 0 and 1; buffers 0-3)
    ISSUE_BODY(0, 0)
    ISSUE_BODY(1, 32)
    CP_COMMIT();
    ISSUE_BODY(2, 64)
    ISSUE_BODY(3, 96)
    CP_COMMIT();

    for (int g = 0; g < G; g++) {
        CP_WAIT1();            // FIFO groups: all but newest commit complete => group g ready
        __syncthreads();
        const int pb = (g % 3) * 2;
        {
            const uint32_t a0 = sb + (uint32_t)pb * STAGE_BYTES;
            COMPUTE_FP16(acc, a0, a0 + 8192u)
            const uint32_t a1 = a0 + STAGE_BYTES;
            COMPUTE_FP16(acc, a1, a1 + 8192u)
        }
        if (g + 2 < G) {
            const int tb = ((g + 2) % 3) * 2;   // disjoint from pairs g, g+1
            ISSUE_BODY(tb,     (g + 2) * 64)
            ISSUE_BODY(tb + 1, (g + 2) * 64 + 32)
        }
        CP_COMMIT();   // unconditional: exact FIFO accounting in the tail
    }

    // ---- write C ----
    if (WRITE_C) {
#pragma unroll
        for (int nj = 0; nj < 4; nj++) {
            const int cc = n0 + warp_n * 32 + nj * 8 + tig * 2;
            float b0 = 0.0f, b1 = 0.0f;
            if (HAS_BIAS) { b0 = bias[cc]; b1 = bias[cc + 1]; }
#pragma unroll
            for (int mi = 0; mi < 4; mi++) {
                const long long r0 = m0 + warp_m * 64 + mi * 16 + grp;
                const long long r1 = r0 + 8;
                const float x0 = alpha * acc[mi][nj][0] + b0;
                const float x1 = alpha * acc[mi][nj][1] + b1;
                const float x2 = alpha * acc[mi][nj][2] + b0;
                const float x3 = alpha * acc[mi][nj][3] + b1;
                if (OUT_HALF) {
                    __half* C = reinterpret_cast<__half*>(Cv) + coff;
                    *reinterpret_cast<uint32_t*>(C + r0 * ldc + cc) = pack_h2(x0, x1);
                    *reinterpret_cast<uint32_t*>(C + r1 * ldc + cc) = pack_h2(x2, x3);
                } else {
                    float* C = reinterpret_cast<float*>(Cv) + coff;
                    *reinterpret_cast<float2*>(C + r0 * ldc + cc) = make_float2(x0, x1);
                    *reinterpret_cast<float2*>(C + r1 * ldc + cc) = make_float2(x2, x3);
                }
            }
        }
    }

    // ---- per-tile softmax stats (scores pass) ----
    if (STATS) {
        __syncthreads();
        float* sred    = reinterpret_cast<float*>(smem);
        float* rowmaxs = reinterpret_cast<float*>(smem) + 512;

#pragma unroll
        for (int mi = 0; mi < 4; mi++) {
#pragma unroll
            for (int h = 0; h < 2; h++) {
                float mx = -1e30f;
#pragma unroll
                for (int nj = 0; nj < 4; nj++)
                    mx = fmaxf(mx, fmaxf(alpha * acc[mi][nj][h * 2],
                                         alpha * acc[mi][nj][h * 2 + 1]));
                mx = fmaxf(mx, __shfl_xor_sync(0xffffffffu, mx, 1));
                mx = fmaxf(mx, __shfl_xor_sync(0xffffffffu, mx, 2));
                const int rl = warp_m * 64 + mi * 16 + grp + h * 8;
                if (tig == 0) sred[warp_n * 128 + rl] = mx;
            }
        }
        __syncthreads();
        if (tid < 128) {
            float rm = fmaxf(fmaxf(sred[tid], sred[128 + tid]),
                             fmaxf(sred[256 + tid], sred[384 + tid]));
            rowmaxs[tid] = rm;
        }
        __syncthreads();

#pragma unroll
        for (int mi = 0; mi < 4; mi++) {
#pragma unroll
            for (int h = 0; h < 2; h++) {
                const int rl = warp_m * 64 + mi * 16 + grp + h * 8;
                const float rm = rowmaxs[rl];
                float s = 0.0f;
#pragma unroll
                for (int nj = 0; nj < 4; nj++) {
                    s += __expf(alpha * acc[mi][nj][h * 2]     - rm);
                    s += __expf(alpha * acc[mi][nj][h * 2 + 1] - rm);
                }
                s += __shfl_xor_sync(0xffffffffu, s, 1);
                s += __shfl_xor_sync(0xffffffffu, s, 2);
                if (tig == 0) sred[warp_n * 128 + rl] = s;
            }
        }
        __syncthreads();
        if (tid < 128) {
            const float sg = sred[tid] + sred[128 + tid] + sred[256 + tid] + sred[384 + tid];
            const long long gi = ((long long)z * SS + m0 + tid) * NTILE + blockIdx.x;
            statsM[gi] = rowmaxs[tid];
            statsS[gi] = sg;
        }
    }
#undef ISSUE_BODY
}

// ============================================================================
// Fused flash attention pass: recompute scores, softmax, write attn, p @ vt.
//   q persistent; k/vt double-buffered; barrier after ctx mma before reissue
//   into the same buffer (R13 race fix). attn written with streaming stores.
// ============================================================================
__global__ __launch_bounds__(256, 1) void attn_flash_kernel(
    const __half* __restrict__ Qp, const __half* __restrict__ Kp,
    const __half* __restrict__ VTp, __half* __restrict__ CTX,
    float* __restrict__ ATTN,
    const float* __restrict__ rowM, const float* __restrict__ rowInv,
    float alpha)
{
    extern __shared__ char smem[];
    const uint32_t sb = smem_u32(smem);

    const int z  = blockIdx.z;
    const int zb = z >> 3;
    const int zh = z & 7;
    const int m0 = blockIdx.y * 128;

    const __half* Qg = Qp + ((long long)zb * SS + m0) * DMODEL + zh * DK;
    const __half* Kg = Kp + (long long)zb * SS * DMODEL + zh * DK;
    const __half* Vg = VTp + (long long)z * DK * SS;
    __half* Cg = CTX + ((long long)zb * SS + m0) * DMODEL + zh * DK;
    float* Ag = ATTN + ((long long)z * SS + m0) * SS;

    const int tid  = threadIdx.x;
    const int wid  = tid >> 5;
    const int lane = tid & 31;
    const int warp_m = wid >> 2;
    const int warp_n = wid & 3;
    const int grp  = lane >> 2;
    const int tig  = lane & 3;

    const int lm  = tid >> 2;
    const int lcw = (tid & 3) * 4;
    const int lch = (tid & 3) * 8;

    LDM_PREP()

    float mlo[4], mhi[4], ilo[4], ihi[4];
#pragma unroll
    for (int mi = 0; mi < 4; mi++) {
        const long long r = (long long)z * SS + m0 + warp_m * 64 + mi * 16 + grp;
        mlo[mi] = rowM[r];     ilo[mi] = rowInv[r];
        mhi[mi] = rowM[r + 8]; ihi[mi] = rowInv[r + 8];
    }

    float cacc[4][4][4];
#pragma unroll
    for (int i = 0; i < 4; i++)
#pragma unroll
        for (int j = 0; j < 4; j++)
#pragma unroll
            for (int q = 0; q < 4; q++) cacc[i][j][q] = 0.0f;

    // ---- load q block (4 dk sub-tiles) ----
#pragma unroll
    for (int t = 0; t < 4; t++)
#pragma unroll
        for (int i = 0; i < 2; i++) {
            const int m = lm + i * 64;
            cp_async16(sb + FA_Q_OFF + t * 8192u + SW_WORD(m, lcw) * 4u,
                       Qg + (long long)m * DMODEL + t * 32 + lch);
        }

#define ISSUE_KV(bufi, s0)                                                      \
    {                                                                           \
        const uint32_t kb_ = sb + FA_KV_OFF + (uint32_t)(bufi) * FA_KV_STAGE;   \
        const uint32_t vb_ = kb_ + 32768u;                                      \
        _Pragma("unroll")                                                       \
        for (int t = 0; t < 4; t++)                                             \
            _Pragma("unroll")                                                   \
            for (int i = 0; i < 2; i++) {                                       \
                const int m = lm + i * 64;                                      \
                cp_async16(kb_ + t * 8192u + SW_WORD(m, lcw) * 4u,              \
                           Kg + (long long)((s0) + m) * DMODEL + t * 32 + lch); \
                cp_async16(vb_ + t * 8192u + SW_WORD(m, lcw) * 4u,              \
                           Vg + (long long)m * SS + (s0) + t * 32 + lch);       \
            }                                                                   \
    }

    ISSUE_KV(0, 0)    CP_COMMIT();
    ISSUE_KV(1, 128)  CP_COMMIT();

    for (int ch = 0; ch < NTILE; ch++) {
        const int s0 = ch * 128;
        const int b  = ch & 1;
        const uint32_t kbuf = sb + FA_KV_OFF + (uint32_t)b * FA_KV_STAGE;
        const uint32_t vbuf = kbuf + 32768u;

        CP_WAIT1();
        __syncthreads();

        // ---- scores tile: q @ k^T ----
        float sacc[4][4][4];
#pragma unroll
        for (int i = 0; i < 4; i++)
#pragma unroll
            for (int j = 0; j < 4; j++)
#pragma unroll
                for (int q = 0; q < 4; q++) sacc[i][j][q] = 0.0f;
#pragma unroll
        for (int t = 0; t < 4; t++) {
            const uint32_t qa = sb + FA_Q_OFF + t * 8192u;
            const uint32_t ka = kbuf + t * 8192u;
            COMPUTE_FP16(sacc, qa, ka)
        }

        // ---- transform: p = exp(alpha*s - M) * inv; stream attn; p -> smem ----
#pragma unroll
        for (int mi = 0; mi < 4; mi++) {
#pragma unroll
            for (int nj = 0; nj < 4; nj++) {
                const int cc = warp_n * 32 + nj * 8 + tig * 2;
                const float p00 = __expf(alpha * sacc[mi][nj][0] - mlo[mi]) * ilo[mi];
                const float p01 = __expf(alpha * sacc[mi][nj][1] - mlo[mi]) * ilo[mi];
                const float p10 = __expf(alpha * sacc[mi][nj][2] - mhi[mi]) * ihi[mi];
                const float p11 = __expf(alpha * sacc[mi][nj][3] - mhi[mi]) * ihi[mi];
                const int rlo = warp_m * 64 + mi * 16 + grp;
                stcs_f2(Ag + (long long)rlo * SS + s0 + cc, p00, p01);
                stcs_f2(Ag + (long long)(rlo + 8) * SS + s0 + cc, p10, p11);
                const uint32_t pw = (uint32_t)(nj * 4 + tig);
                const uint32_t poff = FA_P_OFF + (uint32_t)warp_n * 8192u;
                *reinterpret_cast<uint32_t*>(smem + poff + SW_WORD(rlo, pw) * 4u) =
                    pack_h2(p00, p01);
                *reinterpret_cast<uint32_t*>(smem + poff + SW_WORD(rlo + 8, pw) * 4u) =
                    pack_h2(p10, p11);
            }
        }
        __syncthreads();

        // ---- ctx mma: p @ vt^T ----
#pragma unroll
        for (int t = 0; t < 4; t++) {
            const uint32_t pa = sb + FA_P_OFF + t * 8192u;
            const uint32_t va = vbuf + t * 8192u;
            COMPUTE_FP16(cacc, pa, va)
        }

        // RACE FIX: all warps finish reading buffer b before reissuing into it.
        __syncthreads();

        if (ch + 2 < NTILE) {
            ISSUE_KV(b, (ch + 2) * 128)
        }
        CP_COMMIT();
    }

    // ---- write ctx fp16 ----
#pragma unroll
    for (int nj = 0; nj < 4; nj++) {
        const int cc = warp_n * 32 + nj * 8 + tig * 2;
#pragma unroll
        for (int mi = 0; mi < 4; mi++) {
            const long long r0 = warp_m * 64 + mi * 16 + grp;
            const long long r1 = r0 + 8;
            *reinterpret_cast<uint32_t*>(Cg + r0 * DMODEL + cc) =
                pack_h2(cacc[mi][nj][0], cacc[mi][nj][1]);
            *reinterpret_cast<uint32_t*>(Cg + r1 * DMODEL + cc) =
                pack_h2(cacc[mi][nj][2], cacc[mi][nj][3]);
        }
    }
#undef ISSUE_KV
}

// ============================================================================
// Prepass converters + stats combine + V transpose
// ============================================================================
__global__ __launch_bounds__(256) void cvt_weights_kernel(
    const float* __restrict__ w0, const float* __restrict__ w1,
    const float* __restrict__ w2, const float* __restrict__ w3,
    __half* __restrict__ dst)
{
    const float* src = (blockIdx.z == 0) ? w0 : (blockIdx.z == 1) ? w1
                     : (blockIdx.z == 2) ? w2 : w3;
    __half* d = dst + (size_t)blockIdx.z * DMODEL * DMODEL;
    const long long i = ((long long)blockIdx.x * 256 + threadIdx.x) * 4;
    float4 v = *reinterpret_cast<const float4*>(src + i);
    uint2 u;
    u.x = pack_h2(v.x, v.y);
    u.y = pack_h2(v.z, v.w);
    *reinterpret_cast<uint2*>(d + i) = u;
}

__global__ __launch_bounds__(256) void cvt_inputs_kernel(
    const float* __restrict__ x0, const float* __restrict__ x1,
    const float* __restrict__ x2, __half* __restrict__ dst)
{
    const float* src = (blockIdx.z == 0) ? x0 : (blockIdx.z == 1) ? x1 : x2;
    __half* d = dst + (size_t)blockIdx.z * BB * SS * DMODEL;
    const long long i = ((long long)blockIdx.x * 256 + threadIdx.x) * 4;
    float4 v = *reinterpret_cast<const float4*>(src + i);
    uint2 u;
    u.x = pack_h2(v.x, v.y);
    u.y = pack_h2(v.z, v.w);
    *reinterpret_cast<uint2*>(d + i) = u;
}

__global__ __launch_bounds__(256) void combine_stats_kernel(
    const float* __restrict__ sM, const float* __restrict__ sS,
    float* __restrict__ rowM, float* __restrict__ rowInv)
{
    const long long r = (long long)blockIdx.x * 256 + threadIdx.x;
    const float* pm = sM + r * NTILE;
    const float* ps = sS + r * NTILE;
    float M = -1e30f;
#pragma unroll
    for (int t = 0; t < NTILE; t++) M = fmaxf(M, pm[t]);
    float S = 0.0f;
#pragma unroll
    for (int t = 0; t < NTILE; t++) S += ps[t] * __expf(pm[t] - M);
    rowM[r]   = M;
    rowInv[r] = 1.0f / S;
}

__global__ void transpose_v_kernel(const __half* __restrict__ v, __half* __restrict__ vt)
{
    __shared__ __half t[32][33];
    const int z = blockIdx.z, b = z >> 3, h = z & 7;
    const int s0 = blockIdx.x * 32, n0 = blockIdx.y * 32;
    const int tx = threadIdx.x, ty = threadIdx.y;
#pragma unroll
    for (int j = ty; j < 32; j += 8)
        t[j][tx] = v[((long long)b * SS + s0 + j) * DMODEL + h * DK + n0 + tx];
    __syncthreads();
#pragma unroll
    for (int j = ty; j < 32; j += 8)
        vt[((long long)z * DK + n0 + j) * SS + s0 + tx] = t[tx][j];
}

extern "C" void kernel_launch(void* const* d_in, const int* in_sizes, int n_in,
                              void* d_out, int out_size)
{
    const float* Q  = (const float*)d_in[0];
    const float* K  = (const float*)d_in[1];
    const float* V  = (const float*)d_in[2];
    const float* Wq = (const float*)d_in[3];
    const float* bq = (const float*)d_in[4];
    const float* Wk = (const float*)d_in[5];
    const float* bk = (const float*)d_in[6];
    const float* Wv = (const float*)d_in[7];
    const float* bv = (const float*)d_in[8];
    const float* Wo = (const float*)d_in[9];
    const float* bo = (const float*)d_in[10];

    float* out = (float*)d_out;

    const long long OUT_ELEMS  = (long long)BB * SS * DMODEL;
    const long long ATTN_ELEMS = (long long)NZ * SS * SS;

    __half *qp, *kp, *vp, *vtp, *ctxp, *wp, *inp;
    float *fbp, *sMp, *sSp, *rMp, *rIp;
    cudaGetSymbolAddress((void**)&qp,   g_q);
    cudaGetSymbolAddress((void**)&kp,   g_k);
    cudaGetSymbolAddress((void**)&vp,   g_v);
    cudaGetSymbolAddress((void**)&vtp,  g_vt);
    cudaGetSymbolAddress((void**)&ctxp, g_ctx);
    cudaGetSymbolAddress((void**)&fbp,  g_attn_fb);
    cudaGetSymbolAddress((void**)&sMp,  g_statsM);
    cudaGetSymbolAddress((void**)&sSp,  g_statsS);
    cudaGetSymbolAddress((void**)&rMp,  g_rowM);
    cudaGetSymbolAddress((void**)&rIp,  g_rowInv);
    cudaGetSymbolAddress((void**)&wp,   g_w);
    cudaGetSymbolAddress((void**)&inp,  g_in);

    float* attn = ((long long)out_size >= OUT_ELEMS + ATTN_ELEMS)
                      ? (out + OUT_ELEMS) : fbp;

    // <HAS_BIAS, STATS, OUT_HALF, WRITE_C>
    auto projK  = gemm_fp16_kernel<true,  false, true,  true >;
    auto statsK = gemm_fp16_kernel<false, true,  false, false>;
    auto outK   = gemm_fp16_kernel<true,  false, false, true >;
    cudaFuncSetAttribute(projK,  cudaFuncAttributeMaxDynamicSharedMemorySize, GEMM_SMEM_BYTES);
    cudaFuncSetAttribute(statsK, cudaFuncAttributeMaxDynamicSharedMemorySize, GEMM_SMEM_BYTES);
    cudaFuncSetAttribute(outK,   cudaFuncAttributeMaxDynamicSharedMemorySize, GEMM_SMEM_BYTES);
    cudaFuncSetAttribute(attn_flash_kernel,
                         cudaFuncAttributeMaxDynamicSharedMemorySize, FA_SMEM_BYTES);

    const int M = BB * SS;
    const float inv_sqrt_dk = 0.08838834764831845f;

    dim3 blk(256);

    // 0) prepass: convert weights + inputs to fp16
    {
        dim3 gW(DMODEL * DMODEL / (256 * 4), 1, 4);
        cvt_weights_kernel<<<gW, blk>>>(Wq, Wk, Wv, Wo, wp);
        dim3 gI((BB * SS * DMODEL) / (256 * 4), 1, 3);
        cvt_inputs_kernel<<<gI, blk>>>(Q, K, V, inp);
    }
    __half* wq = wp;
    __half* wk = wp + (size_t)DMODEL * DMODEL;
    __half* wv = wp + 2 * (size_t)DMODEL * DMODEL;
    __half* wo = wp + 3 * (size_t)DMODEL * DMODEL;
    __half* qin = inp;
    __half* kin = inp + (size_t)BB * SS * DMODEL;
    __half* vin = inp + 2 * (size_t)BB * SS * DMODEL;

    // 1-3) projections
    dim3 gProj(DMODEL / 128, M / 128, 1);
    projK<<<gProj, blk, GEMM_SMEM_BYTES>>>(qin, wq, bq, qp,
        DMODEL, DMODEL, DMODEL, DMODEL, 1.0f, 1, 0, 0, 0, 0, 0, 0, nullptr, nullptr);
    projK<<<gProj, blk, GEMM_SMEM_BYTES>>>(kin, wk, bk, kp,
        DMODEL, DMODEL, DMODEL, DMODEL, 1.0f, 1, 0, 0, 0, 0, 0, 0, nullptr, nullptr);
    projK<<<gProj, blk, GEMM_SMEM_BYTES>>>(vin, wv, bv, vp,
        DMODEL, DMODEL, DMODEL, DMODEL, 1.0f, 1, 0, 0, 0, 0, 0, 0, nullptr, nullptr);

    // 3b) transpose V per head
    {
        dim3 gT(SS / 32, DK / 32, NZ);
        dim3 bT(32, 8);
        transpose_v_kernel<<<gT, bT>>>(vp, vtp);
    }

    // 4) stats pass: q @ k^T tile stats only (no score write)
    dim3 gScores(SS / 128, SS / 128, NZ);
    statsK<<<gScores, blk, GEMM_SMEM_BYTES>>>(qp, kp, nullptr, nullptr,
        DK, DMODEL, DMODEL, SS, inv_sqrt_dk,
        NHEADS,
        (long long)SS * DMODEL, (long long)DK,
        (long long)SS * DMODEL, (long long)DK,
        0, 0,
        sMp, sSp);

    // 5) combine stats
    combine_stats_kernel<<<(NZ * SS) / 256, blk>>>(sMp, sSp, rMp, rIp);

    // 6) fused flash pass
    {
        dim3 gF(1, SS / 128, NZ);
        attn_flash_kernel<<<gF, blk, FA_SMEM_BYTES>>>(qp, kp, vtp, ctxp, attn,
                                                      rMp, rIp, inv_sqrt_dk);
    }

    // 7) out = ctx @ Wo^T + bo
    outK<<<gProj, blk, GEMM_SMEM_BYTES>>>(ctxp, wo, bo, out,
        DMODEL, DMODEL, DMODEL, DMODEL, 1.0f, 1, 0, 0, 0, 0, 0, 0, nullptr, nullptr);
}